// round 6
// baseline (speedup 1.0000x reference)
#include <cuda_runtime.h>
#include <cuda_bf16.h>
#include <cstdint>

#define B_ 256
#define H_ 1024
#define D_ 256
#define C_ 16
#define G_ 32
#define O_ 256
#define HD_ 1280  // H + D

// ---------------- device-global scratch (no cudaMalloc allowed) ----------------
__device__ float g_ebias[C_ * G_ * H_];    // [c][g][h]
__device__ float g_hid[B_ * C_ * H_];      // [b][c][h]
__device__ float g_scores[B_ * C_ * G_];   // [b][c][g]
__device__ float g_pooled[B_ * D_];        // [b][d]

// bf16 hi/lo split of A (hidden) only — W is split on the fly inside the GEMM.
__device__ uint4 g_ah[B_ * H_ / 8];        // A hi  [m][k]   0.5 MB
__device__ uint4 g_al[B_ * H_ / 8];        // A lo

// ---------------- helpers ----------------
__device__ __forceinline__ uint32_t smem_u32(const void* p) {
    uint32_t a;
    asm("{ .reg .u64 t; cvta.to.shared.u64 t, %1; cvt.u32.u64 %0, t; }"
        : "=r"(a) : "l"(p));
    return a;
}
__device__ __forceinline__ void cp16(uint32_t dst, const void* src) {
    asm volatile("cp.async.cg.shared.global [%0], [%1], 16;"
                 :: "r"(dst), "l"(src) : "memory");
}
__device__ __forceinline__ void ldsm4(uint32_t* r, uint32_t addr) {
    asm volatile("ldmatrix.sync.aligned.m8n8.x4.shared.b16 {%0,%1,%2,%3}, [%4];"
                 : "=r"(r[0]), "=r"(r[1]), "=r"(r[2]), "=r"(r[3]) : "r"(addr));
}
__device__ __forceinline__ void mma16816(float* d, const uint32_t* a, const uint32_t* b) {
    asm volatile(
        "mma.sync.aligned.m16n8k16.row.col.f32.bf16.bf16.f32 "
        "{%0,%1,%2,%3}, {%4,%5,%6,%7}, {%8,%9}, {%0,%1,%2,%3};"
        : "+f"(d[0]), "+f"(d[1]), "+f"(d[2]), "+f"(d[3])
        : "r"(a[0]), "r"(a[1]), "r"(a[2]), "r"(a[3]), "r"(b[0]), "r"(b[1]));
}
// Accurate tanh: 2 MUFU, ~1e-7 abs error, correct saturation.
__device__ __forceinline__ float tanh_fast(float x) {
    float e, r;
    asm("ex2.approx.f32 %0, %1;" : "=f"(e) : "f"(x * 2.8853900817779268f));
    asm("rcp.approx.f32 %0, %1;" : "=f"(r) : "f"(e + 1.0f));
    return fmaf(-2.0f, r, 1.0f);
}
__device__ __forceinline__ void split8(const float* xs, uint32_t* hw, uint32_t* lw) {
    #pragma unroll
    for (int i = 0; i < 4; i++) {
        __nv_bfloat16 h0 = __float2bfloat16(xs[2*i]);
        __nv_bfloat16 h1 = __float2bfloat16(xs[2*i+1]);
        __nv_bfloat16 l0 = __float2bfloat16(xs[2*i]   - __bfloat162float(h0));
        __nv_bfloat16 l1 = __float2bfloat16(xs[2*i+1] - __bfloat162float(h1));
        hw[i] = (uint32_t)__bfloat16_as_ushort(h0) | ((uint32_t)__bfloat16_as_ushort(h1) << 16);
        lw[i] = (uint32_t)__bfloat16_as_ushort(l0) | ((uint32_t)__bfloat16_as_ushort(l1) << 16);
    }
}

// ---------------- K0: split hidden -> bf16 hi/lo ----------------
__global__ void __launch_bounds__(256) convert_a_kernel(const float* __restrict__ hidden)
{
    int idx = blockIdx.x * 256 + threadIdx.x;   // 32768
    int b = idx >> 7, j = idx & 127;
    const float4* s = (const float4*)(hidden + (size_t)b * H_ + j * 8);
    float4 x0 = s[0], x1 = s[1];
    float xs[8] = {x0.x, x0.y, x0.z, x0.w, x1.x, x1.y, x1.z, x1.w};
    uint32_t hw[4], lw[4];
    split8(xs, hw, lw);
    g_ah[b * 128 + j] = make_uint4(hw[0], hw[1], hw[2], hw[3]);
    g_al[b * 128 + j] = make_uint4(lw[0], lw[1], lw[2], lw[3]);
}

// ---------------- K1: ebias ----------------
__global__ void __launch_bounds__(256) ebias_kernel(
    const float* __restrict__ gst_emb, const float* __restrict__ attn_w,
    const float* __restrict__ attn_b)
{
    int c = blockIdx.x;
    int o = blockIdx.y * 128 + (threadIdx.x & 127);
    int gbase = (threadIdx.x >> 7) * 16;
    __shared__ float gs[G_][D_];
    const float4* src = (const float4*)(gst_emb + (size_t)c * G_ * D_);
    for (int i = threadIdx.x; i < G_ * D_ / 4; i += 256)
        ((float4*)gs)[i] = src[i];
    __syncthreads();

    float acc[16];
    #pragma unroll
    for (int g = 0; g < 16; g++) acc[g] = 0.f;

    const float* wrow = attn_w + (size_t)c * H_ * HD_ + (size_t)o * HD_ + H_;
    for (int d = 0; d < D_; d += 4) {
        float4 w4 = *(const float4*)(wrow + d);
        #pragma unroll
        for (int g = 0; g < 16; g++) {
            float a = acc[g];
            a = fmaf(gs[gbase + g][d],     w4.x, a);
            a = fmaf(gs[gbase + g][d + 1], w4.y, a);
            a = fmaf(gs[gbase + g][d + 2], w4.z, a);
            a = fmaf(gs[gbase + g][d + 3], w4.w, a);
            acc[g] = a;
        }
    }
    float bias = attn_b[c * H_ + o];
    #pragma unroll
    for (int g = 0; g < 16; g++)
        g_ebias[(size_t)c * G_ * H_ + (size_t)(gbase + g) * H_ + o] = acc[g] + bias;
}

// ---------------- K2: hid_part GEMM, bf16 hi/lo split done IN-KERNEL ----------------
// grid (8, 2, 16): BN=128, BM=128, per c. 8 warps: wm in {0,1}, wn in 0..3 (32 cols).
// B (= w_hid) is loaded as fp32 via cp.async into a swizzled staging buffer, then
// split into bf16 hi/lo operand tiles in smem each stage.
#define LDROW 80                    // operand smem row stride bytes (32 bf16 + 16B pad)
#define TILEB (128 * LDROW)         // 10240
#define STAGEB (4 * TILEB)          // Ah, Al, Bh, Bl = 40960
#define FOFF  (2 * STAGEB)          // 81920: fp32 B staging base
#define FSTAGE 16384                // 128 rows x 32 floats
#define GSMEM (FOFF + 2 * FSTAGE)   // 114688
#define NKC 32                      // K / 32

__global__ void __launch_bounds__(256) gemm_mma_kernel(const float* __restrict__ attn_w)
{
    extern __shared__ char smem[];
    uint32_t sb = smem_u32(smem);
    int t = threadIdx.x, w = t >> 5, l = t & 31;
    int wm = w & 1, wn = w >> 1;
    int bn0 = blockIdx.x * 128, bm0 = blockIdx.y * 128, c = blockIdx.z;

    const uint4*  pAh = g_ah + (size_t)bm0 * 128;
    const uint4*  pAl = g_al + (size_t)bm0 * 128;
    const float*  pW  = attn_w + (size_t)c * H_ * HD_ + (size_t)bn0 * HD_;

    int arow = t >> 2, aq = t & 3;   // A copy: 64 rows x 4 chunks, 2 halves
    int brow = t >> 1, bhf = t & 1;  // B copy/convert: 128 rows x 2 halves (16 floats each)
    const float* bsrc_row = pW + (size_t)brow * HD_ + bhf * 16;

    float acc[4][4][4];
    #pragma unroll
    for (int i = 0; i < 4; i++)
        #pragma unroll
        for (int j = 0; j < 4; j++)
            #pragma unroll
            for (int k = 0; k < 4; k++) acc[i][j][k] = 0.f;

    // async-load one stage: A bf16 hi/lo (pre-split) + B fp32 (swizzled staging)
    auto stage_load = [&](int kc, int buf) {
        uint32_t base = sb + buf * STAGEB;
        #pragma unroll
        for (int h = 0; h < 2; h++) {
            int r = arow + h * 64;
            int su = r * 128 + kc * 4 + aq;
            uint32_t d = base + (uint32_t)(r * LDROW + aq * 16);
            cp16(d,         pAh + su);
            cp16(d + TILEB, pAl + su);
        }
        uint32_t fb = sb + FOFF + buf * FSTAGE;
        const float* src = bsrc_row + kc * 32;
        #pragma unroll
        for (int j = 0; j < 4; j++) {
            uint32_t off = (uint32_t)(brow * 128 + bhf * 64 + j * 16);
            uint32_t sw  = off ^ ((off >> 3) & 0x70);
            cp16(fb + sw, src + j * 4);
        }
    };

    stage_load(0, 0);
    asm volatile("cp.async.commit_group;" ::: "memory");
    stage_load(1, 1);
    asm volatile("cp.async.commit_group;" ::: "memory");

    uint32_t arow_off = (uint32_t)((l & 15) * LDROW + (l >> 4) * 16);
    uint32_t brow_off = (uint32_t)((((l & 7) + ((l >> 4) << 3)) * LDROW) + ((l >> 3) & 1) * 16);

    for (int kc = 0; kc < NKC; kc++) {
        int cur = kc & 1;
        asm volatile("cp.async.wait_group 1;" ::: "memory");
        __syncthreads();

        // ---- convert this stage's fp32 B chunk -> bf16 hi/lo operand tiles ----
        {
            char* fb = smem + FOFF + cur * FSTAGE;
            float f[16];
            #pragma unroll
            for (int j = 0; j < 4; j++) {
                uint32_t off = (uint32_t)(brow * 128 + bhf * 64 + j * 16);
                uint32_t sw  = off ^ ((off >> 3) & 0x70);
                float4 v4 = *(const float4*)(fb + sw);
                f[j*4+0] = v4.x; f[j*4+1] = v4.y; f[j*4+2] = v4.z; f[j*4+3] = v4.w;
            }
            uint32_t hw[8], lw[8];
            split8(f,     hw,     lw);
            split8(f + 8, hw + 4, lw + 4);
            char* ob = smem + (size_t)cur * STAGEB;
            uint32_t doff = (uint32_t)(brow * LDROW + bhf * 32);
            *(uint4*)(ob + 2 * TILEB + doff)      = make_uint4(hw[0], hw[1], hw[2], hw[3]);
            *(uint4*)(ob + 2 * TILEB + doff + 16) = make_uint4(hw[4], hw[5], hw[6], hw[7]);
            *(uint4*)(ob + 3 * TILEB + doff)      = make_uint4(lw[0], lw[1], lw[2], lw[3]);
            *(uint4*)(ob + 3 * TILEB + doff + 16) = make_uint4(lw[4], lw[5], lw[6], lw[7]);
        }
        __syncthreads();

        // ---- MMA on the converted stage ----
        uint32_t base = sb + cur * STAGEB;
        #pragma unroll
        for (int kk = 0; kk < 2; kk++) {
            uint32_t kkb = kk * 32;
            uint32_t aH[4][4], aL[4][4], bH[2][4], bL[2][4];
            #pragma unroll
            for (int mt = 0; mt < 4; mt++) {
                uint32_t ad = base + (uint32_t)((wm * 64 + mt * 16) * LDROW) + kkb + arow_off;
                ldsm4(aH[mt], ad);
                ldsm4(aL[mt], ad + TILEB);
            }
            #pragma unroll
            for (int p = 0; p < 2; p++) {
                uint32_t bd = base + 2 * TILEB +
                              (uint32_t)((wn * 32 + p * 16) * LDROW) + kkb + brow_off;
                ldsm4(bH[p], bd);
                ldsm4(bL[p], bd + TILEB);
            }
            #pragma unroll
            for (int mt = 0; mt < 4; mt++)
                #pragma unroll
                for (int p = 0; p < 2; p++)
                    #pragma unroll
                    for (int hf = 0; hf < 2; hf++) {
                        int nt = p * 2 + hf;
                        mma16816(acc[mt][nt], aH[mt], &bH[p][hf * 2]);
                        mma16816(acc[mt][nt], aH[mt], &bL[p][hf * 2]);
                        mma16816(acc[mt][nt], aL[mt], &bH[p][hf * 2]);
                    }
        }
        __syncthreads();   // protect buffers before refill

        if (kc + 2 < NKC) stage_load(kc + 2, cur);
        asm volatile("cp.async.commit_group;" ::: "memory");  // (empty group at tail)
    }

    // epilogue -> g_hid[b][c][h]
    #pragma unroll
    for (int mt = 0; mt < 4; mt++) {
        int m0 = bm0 + wm * 64 + mt * 16 + (l >> 2);
        #pragma unroll
        for (int nt = 0; nt < 4; nt++) {
            int col = bn0 + wn * 32 + nt * 8 + (l & 3) * 2;
            float* d0 = g_hid + (size_t)m0 * (C_ * H_) + (size_t)c * H_ + col;
            *(float2*)d0 = make_float2(acc[mt][nt][0], acc[mt][nt][1]);
            *(float2*)(d0 + (size_t)8 * C_ * H_) = make_float2(acc[mt][nt][2], acc[mt][nt][3]);
        }
    }
}

// ---------------- K3: scores ----------------
__global__ void __launch_bounds__(256) scores_kernel(const float* __restrict__ v)
{
    int c = blockIdx.x;
    int b0 = blockIdx.y * 16;
    __shared__ float hidS[16][65];
    __shared__ float ebS[32][65];
    __shared__ float vS[64];
    int t = threadIdx.x;
    int bb = t & 15;
    int q  = t >> 4;
    float acc0 = 0.f, acc1 = 0.f;

    for (int hc = 0; hc < H_; hc += 64) {
        {
            int i = t >> 4, j4 = (t & 15) * 4;
            float4 hv = *(const float4*)(g_hid + (size_t)(b0 + i) * (C_ * H_) + (size_t)c * H_ + hc + j4);
            hidS[i][j4] = hv.x; hidS[i][j4+1] = hv.y; hidS[i][j4+2] = hv.z; hidS[i][j4+3] = hv.w;
        }
        #pragma unroll
        for (int p = 0; p < 2; p++) {
            int idx = t + p * 256;
            int g = idx >> 4, j4 = (idx & 15) * 4;
            float4 ev = *(const float4*)(g_ebias + (size_t)c * (G_ * H_) + (size_t)g * H_ + hc + j4);
            ebS[g][j4] = ev.x; ebS[g][j4+1] = ev.y; ebS[g][j4+2] = ev.z; ebS[g][j4+3] = ev.w;
        }
        if (t < 16) {
            float4 vv = *(const float4*)(v + (size_t)c * H_ + hc + t * 4);
            vS[t*4] = vv.x; vS[t*4+1] = vv.y; vS[t*4+2] = vv.z; vS[t*4+3] = vv.w;
        }
        __syncthreads();
        #pragma unroll 8
        for (int j = 0; j < 64; j++) {
            float x  = hidS[bb][j];
            float vv = vS[j];
            acc0 = fmaf(vv, tanh_fast(x + ebS[q][j]),      acc0);
            acc1 = fmaf(vv, tanh_fast(x + ebS[q + 16][j]), acc1);
        }
        __syncthreads();
    }
    g_scores[(size_t)(b0 + bb) * (C_ * G_) + c * G_ + q]      = acc0;
    g_scores[(size_t)(b0 + bb) * (C_ * G_) + c * G_ + q + 16] = acc1;
}

// ---------------- K4a: softmax ----------------
__global__ void __launch_bounds__(512) softmax_kernel(float* __restrict__ att)
{
    int b = blockIdx.x;
    int c = threadIdx.x >> 5;
    int g = threadIdx.x & 31;
    float s = g_scores[(size_t)b * (C_ * G_) + c * G_ + g];
    float m = s;
    #pragma unroll
    for (int off = 16; off > 0; off >>= 1)
        m = fmaxf(m, __shfl_xor_sync(0xffffffffu, m, off));
    float e = __expf(s - m);
    float sum = e;
    #pragma unroll
    for (int off = 16; off > 0; off >>= 1)
        sum += __shfl_xor_sync(0xffffffffu, sum, off);
    att[(size_t)b * (C_ * G_) + c * G_ + g] = e / sum;
}

// ---------------- K4b: pooled ----------------
__global__ void __launch_bounds__(256) pooled_kernel(
    const float* __restrict__ att, const float* __restrict__ gst_emb)
{
    int b0 = blockIdx.x * 8;
    int d = threadIdx.x;
    __shared__ float attS[8][C_ * G_];
    #pragma unroll
    for (int p = 0; p < 16; p++) {
        int idx = threadIdx.x + p * 256;
        attS[idx >> 9][idx & 511] = att[(size_t)b0 * 512 + idx];
    }
    __syncthreads();
    float acc[8];
    #pragma unroll
    for (int i = 0; i < 8; i++) acc[i] = 0.f;
    for (int cg = 0; cg < C_ * G_; cg++) {
        float e = gst_emb[(size_t)cg * D_ + d];
        #pragma unroll
        for (int i = 0; i < 8; i++) acc[i] = fmaf(attS[i][cg], e, acc[i]);
    }
    #pragma unroll
    for (int i = 0; i < 8; i++)
        g_pooled[(size_t)(b0 + i) * D_ + d] = acc[i] * (1.0f / C_);
}

// ---------------- K4c: out ----------------
__global__ void __launch_bounds__(256) out_kernel(
    const float* __restrict__ out_w, const float* __restrict__ out_b,
    float* __restrict__ outp)
{
    int b0 = blockIdx.x * 8;
    int o = threadIdx.x;
    __shared__ float ps[8][D_];
    #pragma unroll
    for (int p = 0; p < 8; p++) {
        int idx = threadIdx.x + p * 256;
        ps[idx >> 8][idx & 255] = g_pooled[(size_t)b0 * D_ + idx];
    }
    __syncthreads();
    float acc[8];
    #pragma unroll
    for (int i = 0; i < 8; i++) acc[i] = 0.f;
    const float* wrow = out_w + (size_t)o * D_;
    for (int dd = 0; dd < D_; dd += 4) {
        float4 w4 = *(const float4*)(wrow + dd);
        #pragma unroll
        for (int i = 0; i < 8; i++) {
            float a = acc[i];
            a = fmaf(ps[i][dd],     w4.x, a);
            a = fmaf(ps[i][dd + 1], w4.y, a);
            a = fmaf(ps[i][dd + 2], w4.z, a);
            a = fmaf(ps[i][dd + 3], w4.w, a);
            acc[i] = a;
        }
    }
    float bias = out_b[o];
    #pragma unroll
    for (int i = 0; i < 8; i++)
        outp[(size_t)(b0 + i) * O_ + o] = acc[i] + bias;
}

extern "C" void kernel_launch(void* const* d_in, const int* in_sizes, int n_in,
                              void* d_out, int out_size)
{
    const float* hidden  = (const float*)d_in[0];
    const float* gst_emb = (const float*)d_in[1];
    const float* attn_w  = (const float*)d_in[2];
    const float* attn_b  = (const float*)d_in[3];
    const float* v       = (const float*)d_in[4];
    const float* out_w   = (const float*)d_in[5];
    const float* out_b   = (const float*)d_in[6];
    float* out  = (float*)d_out;
    float* att  = out;                   // [B, C*G]
    float* outp = out + B_ * C_ * G_;    // [B, O]

    cudaFuncSetAttribute(gemm_mma_kernel,
                         cudaFuncAttributeMaxDynamicSharedMemorySize, GSMEM);

    convert_a_kernel<<<128, 256>>>(hidden);
    ebias_kernel    <<<dim3(C_, 8), 256>>>(gst_emb, attn_w, attn_b);
    gemm_mma_kernel <<<dim3(8, 2, C_), 256, GSMEM>>>(attn_w);
    scores_kernel   <<<dim3(C_, 16), 256>>>(v);
    softmax_kernel  <<<B_, 512>>>(att);
    pooled_kernel   <<<B_ / 8, 256>>>(att, gst_emb);
    out_kernel      <<<B_ / 8, 256>>>(out_w, out_b, outp);
}

// round 7
// speedup vs baseline: 1.0757x; 1.0757x over previous
#include <cuda_runtime.h>
#include <cuda_bf16.h>
#include <cstdint>

#define B_ 256
#define H_ 1024
#define D_ 256
#define C_ 16
#define G_ 32
#define O_ 256
#define HD_ 1280  // H + D

// ---------------- device-global scratch (no cudaMalloc allowed) ----------------
__device__ float g_hid[B_ * C_ * H_];      // [b][c][h]  = exp2(2.885 * hid_part)
__device__ float g_ebias[C_ * G_ * H_];    // [c][g][h]  = exp2(2.885 * (enc_part + bias))
__device__ float g_pooled[B_ * D_];        // [b][d]

// bf16 hi/lo split operands, plain row-major (k contiguous).
__device__ uint4 g_ah[B_ * H_ / 8];            // A hi  [m][k]   0.5 MB
__device__ uint4 g_al[B_ * H_ / 8];            // A lo
__device__ uint4 g_wh[C_ * H_ * H_ / 8];       // W hi  [c][n][k]  32 MB
__device__ uint4 g_wl[C_ * H_ * H_ / 8];       // W lo

// ---------------- helpers ----------------
__device__ __forceinline__ uint32_t smem_u32(const void* p) {
    uint32_t a;
    asm("{ .reg .u64 t; cvta.to.shared.u64 t, %1; cvt.u32.u64 %0, t; }"
        : "=r"(a) : "l"(p));
    return a;
}
__device__ __forceinline__ void cp16(uint32_t dst, const void* src) {
    asm volatile("cp.async.cg.shared.global [%0], [%1], 16;"
                 :: "r"(dst), "l"(src) : "memory");
}
__device__ __forceinline__ void ldsm4(uint32_t* r, uint32_t addr) {
    asm volatile("ldmatrix.sync.aligned.m8n8.x4.shared.b16 {%0,%1,%2,%3}, [%4];"
                 : "=r"(r[0]), "=r"(r[1]), "=r"(r[2]), "=r"(r[3]) : "r"(addr));
}
__device__ __forceinline__ void mma16816(float* d, const uint32_t* a, const uint32_t* b) {
    asm volatile(
        "mma.sync.aligned.m16n8k16.row.col.f32.bf16.bf16.f32 "
        "{%0,%1,%2,%3}, {%4,%5,%6,%7}, {%8,%9}, {%0,%1,%2,%3};"
        : "+f"(d[0]), "+f"(d[1]), "+f"(d[2]), "+f"(d[3])
        : "r"(a[0]), "r"(a[1]), "r"(a[2]), "r"(a[3]), "r"(b[0]), "r"(b[1]));
}
// exp2 via MUFU
__device__ __forceinline__ float ex2f(float x) {
    float r;
    asm("ex2.approx.f32 %0, %1;" : "=f"(r) : "f"(x));
    return r;
}
#define TANH_SCALE 2.8853900817779268f   // 2 * log2(e)

__device__ __forceinline__ void split8(const float* xs, uint32_t* hw, uint32_t* lw) {
    #pragma unroll
    for (int i = 0; i < 4; i++) {
        __nv_bfloat16 h0 = __float2bfloat16(xs[2*i]);
        __nv_bfloat16 h1 = __float2bfloat16(xs[2*i+1]);
        __nv_bfloat16 l0 = __float2bfloat16(xs[2*i]   - __bfloat162float(h0));
        __nv_bfloat16 l1 = __float2bfloat16(xs[2*i+1] - __bfloat162float(h1));
        hw[i] = (uint32_t)__bfloat16_as_ushort(h0) | ((uint32_t)__bfloat16_as_ushort(h1) << 16);
        lw[i] = (uint32_t)__bfloat16_as_ushort(l0) | ((uint32_t)__bfloat16_as_ushort(l1) << 16);
    }
}

// ---------------- K0a: split hidden -> bf16 hi/lo ----------------
__global__ void __launch_bounds__(256) convert_a_kernel(const float* __restrict__ hidden)
{
    int idx = blockIdx.x * 256 + threadIdx.x;   // 32768
    int b = idx >> 7, j = idx & 127;
    const float4* s = (const float4*)(hidden + (size_t)b * H_ + j * 8);
    float4 x0 = s[0], x1 = s[1];
    float xs[8] = {x0.x, x0.y, x0.z, x0.w, x1.x, x1.y, x1.z, x1.w};
    uint32_t hw[4], lw[4];
    split8(xs, hw, lw);
    g_ah[b * 128 + j] = make_uint4(hw[0], hw[1], hw[2], hw[3]);
    g_al[b * 128 + j] = make_uint4(lw[0], lw[1], lw[2], lw[3]);
}

// ---------------- K0b: split w_hid -> bf16 hi/lo ----------------
__global__ void __launch_bounds__(256) convert_w_kernel(const float* __restrict__ attn_w)
{
    int idx = blockIdx.x * 256 + threadIdx.x;   // 2,097,152
    int j = idx & 127;
    int o = (idx >> 7) & 1023;
    int c = idx >> 17;
    const float4* s = (const float4*)(attn_w + ((size_t)c * H_ + o) * HD_ + j * 8);
    float4 x0 = s[0], x1 = s[1];
    float xs[8] = {x0.x, x0.y, x0.z, x0.w, x1.x, x1.y, x1.z, x1.w};
    uint32_t hw[4], lw[4];
    split8(xs, hw, lw);
    size_t u = (size_t)c * 131072 + (size_t)o * 128 + j;
    g_wh[u] = make_uint4(hw[0], hw[1], hw[2], hw[3]);
    g_wl[u] = make_uint4(lw[0], lw[1], lw[2], lw[3]);
}

// ---------------- K1: ebias -> exp2 domain ----------------
__global__ void __launch_bounds__(256) ebias_kernel(
    const float* __restrict__ gst_emb, const float* __restrict__ attn_w,
    const float* __restrict__ attn_b)
{
    int c = blockIdx.x;
    int o = blockIdx.y * 128 + (threadIdx.x & 127);
    int gbase = (threadIdx.x >> 7) * 16;
    __shared__ float gs[G_][D_];
    const float4* src = (const float4*)(gst_emb + (size_t)c * G_ * D_);
    for (int i = threadIdx.x; i < G_ * D_ / 4; i += 256)
        ((float4*)gs)[i] = src[i];
    __syncthreads();

    float acc[16];
    #pragma unroll
    for (int g = 0; g < 16; g++) acc[g] = 0.f;

    const float* wrow = attn_w + (size_t)c * H_ * HD_ + (size_t)o * HD_ + H_;
    for (int d = 0; d < D_; d += 4) {
        float4 w4 = *(const float4*)(wrow + d);
        #pragma unroll
        for (int g = 0; g < 16; g++) {
            float a = acc[g];
            a = fmaf(gs[gbase + g][d],     w4.x, a);
            a = fmaf(gs[gbase + g][d + 1], w4.y, a);
            a = fmaf(gs[gbase + g][d + 2], w4.z, a);
            a = fmaf(gs[gbase + g][d + 3], w4.w, a);
            acc[g] = a;
        }
    }
    float bias = attn_b[c * H_ + o];
    #pragma unroll
    for (int g = 0; g < 16; g++)
        g_ebias[(size_t)c * G_ * H_ + (size_t)(gbase + g) * H_ + o] =
            ex2f((acc[g] + bias) * TANH_SCALE);
}

// ---------------- K2: hid_part GEMM via mma.sync bf16 hi/lo (R5 structure) ----------------
// Epilogue writes exp2(2.885 * acc) — the Eh factor consumed by the scores kernel.
#define LDROW 80
#define TILEB (128 * LDROW)
#define STAGEB (4 * TILEB)
#define GSMEM (2 * STAGEB)          // 81920
#define NKC 32

__global__ void __launch_bounds__(256) gemm_mma_kernel()
{
    extern __shared__ char smem[];
    uint32_t sb = smem_u32(smem);
    int t = threadIdx.x, w = t >> 5, l = t & 31;
    int wm = w & 1, wn = w >> 1;
    int bn0 = blockIdx.x * 128, bm0 = blockIdx.y * 128, c = blockIdx.z;

    const uint4* pAh = g_ah + (size_t)bm0 * 128;
    const uint4* pAl = g_al + (size_t)bm0 * 128;
    const uint4* pBh = g_wh + (size_t)c * 131072 + (size_t)bn0 * 128;
    const uint4* pBl = g_wl + (size_t)c * 131072 + (size_t)bn0 * 128;

    int row = t >> 2, q = t & 3;
    uint32_t cpdst = (uint32_t)(row * LDROW + q * 16);

    float acc[4][4][4];
    #pragma unroll
    for (int i = 0; i < 4; i++)
        #pragma unroll
        for (int j = 0; j < 4; j++)
            #pragma unroll
            for (int k = 0; k < 4; k++) acc[i][j][k] = 0.f;

    auto stage_load = [&](int kc, int buf) {
        uint32_t base = sb + buf * STAGEB;
        #pragma unroll
        for (int h = 0; h < 2; h++) {
            int r = row + h * 64;
            int su = r * 128 + kc * 4 + q;
            uint32_t d = base + cpdst + h * 64 * LDROW;
            cp16(d,              pAh + su);
            cp16(d + TILEB,      pAl + su);
            cp16(d + 2 * TILEB,  pBh + su);
            cp16(d + 3 * TILEB,  pBl + su);
        }
        asm volatile("cp.async.commit_group;" ::: "memory");
    };

    stage_load(0, 0);

    uint32_t arow_off = (uint32_t)((l & 15) * LDROW + (l >> 4) * 16);
    uint32_t brow_off = (uint32_t)((((l & 7) + ((l >> 4) << 3)) * LDROW) + ((l >> 3) & 1) * 16);

    for (int kc = 0; kc < NKC; kc++) {
        int cur = kc & 1;
        if (kc + 1 < NKC) {
            stage_load(kc + 1, cur ^ 1);
            asm volatile("cp.async.wait_group 1;" ::: "memory");
        } else {
            asm volatile("cp.async.wait_group 0;" ::: "memory");
        }
        __syncthreads();

        uint32_t base = sb + cur * STAGEB;
        #pragma unroll
        for (int kk = 0; kk < 2; kk++) {
            uint32_t kkb = kk * 32;
            uint32_t aH[4][4], aL[4][4], bH[2][4], bL[2][4];
            #pragma unroll
            for (int mt = 0; mt < 4; mt++) {
                uint32_t ad = base + (uint32_t)((wm * 64 + mt * 16) * LDROW) + kkb + arow_off;
                ldsm4(aH[mt], ad);
                ldsm4(aL[mt], ad + TILEB);
            }
            #pragma unroll
            for (int p = 0; p < 2; p++) {
                uint32_t bd = base + 2 * TILEB +
                              (uint32_t)((wn * 32 + p * 16) * LDROW) + kkb + brow_off;
                ldsm4(bH[p], bd);
                ldsm4(bL[p], bd + TILEB);
            }
            #pragma unroll
            for (int mt = 0; mt < 4; mt++)
                #pragma unroll
                for (int p = 0; p < 2; p++)
                    #pragma unroll
                    for (int hf = 0; hf < 2; hf++) {
                        int nt = p * 2 + hf;
                        mma16816(acc[mt][nt], aH[mt], &bH[p][hf * 2]);
                        mma16816(acc[mt][nt], aH[mt], &bL[p][hf * 2]);
                        mma16816(acc[mt][nt], aL[mt], &bH[p][hf * 2]);
                    }
        }
        __syncthreads();
    }

    // epilogue: Eh = exp2(2.885 * acc) -> g_hid[b][c][h]
    #pragma unroll
    for (int mt = 0; mt < 4; mt++) {
        int m0 = bm0 + wm * 64 + mt * 16 + (l >> 2);
        #pragma unroll
        for (int nt = 0; nt < 4; nt++) {
            int col = bn0 + wn * 32 + nt * 8 + (l & 3) * 2;
            float* d0 = g_hid + (size_t)m0 * (C_ * H_) + (size_t)c * H_ + col;
            *(float2*)d0 = make_float2(ex2f(acc[mt][nt][0] * TANH_SCALE),
                                       ex2f(acc[mt][nt][1] * TANH_SCALE));
            *(float2*)(d0 + (size_t)8 * C_ * H_) =
                make_float2(ex2f(acc[mt][nt][2] * TANH_SCALE),
                            ex2f(acc[mt][nt][3] * TANH_SCALE));
        }
    }
}

// ---------------- K3: fused scores + softmax ----------------
// grid (C, 32): 8 b x 32 g per block; t = bb*32 + g so each warp owns one b row
// and all 32 g -> warp-shuffle softmax at the end, writes att directly.
// tanh(x) = 1 - 2/(1 + Eh*Ee) with Eh, Ee precomputed in exp2 domain: 1 MUFU/elem.
__global__ void __launch_bounds__(256) scores_softmax_kernel(
    const float* __restrict__ v, float* __restrict__ att)
{
    int c = blockIdx.x;
    int b0 = blockIdx.y * 8;
    __shared__ float ehS[8][129];
    __shared__ float eeS[32][129];
    __shared__ float vS[128];
    int t = threadIdx.x;
    int g = t & 31, bb = t >> 5;
    float acc = 0.f;

    for (int hc = 0; hc < H_; hc += 128) {
        {   // Eh tile: 8 rows x 128
            int r = t >> 5, j4 = (t & 31) * 4;
            float4 hv = *(const float4*)(g_hid + (size_t)(b0 + r) * (C_ * H_) +
                                         (size_t)c * H_ + hc + j4);
            ehS[r][j4] = hv.x; ehS[r][j4+1] = hv.y; ehS[r][j4+2] = hv.z; ehS[r][j4+3] = hv.w;
        }
        #pragma unroll
        for (int p = 0; p < 4; p++) {   // Ee tile: 32 rows x 128
            int idx = t + p * 256;
            int r = idx >> 5, j4 = (idx & 31) * 4;
            float4 ev = *(const float4*)(g_ebias + (size_t)c * (G_ * H_) +
                                         (size_t)r * H_ + hc + j4);
            eeS[r][j4] = ev.x; eeS[r][j4+1] = ev.y; eeS[r][j4+2] = ev.z; eeS[r][j4+3] = ev.w;
        }
        if (t < 32) {
            float4 vv = *(const float4*)(v + (size_t)c * H_ + hc + t * 4);
            vS[t*4] = vv.x; vS[t*4+1] = vv.y; vS[t*4+2] = vv.z; vS[t*4+3] = vv.w;
        }
        __syncthreads();
        #pragma unroll 4
        for (int j = 0; j < 128; j++) {
            float e = ehS[bb][j] * eeS[g][j];
            float r;
            asm("rcp.approx.f32 %0, %1;" : "=f"(r) : "f"(e + 1.0f));
            acc = fmaf(vS[j], fmaf(-2.0f, r, 1.0f), acc);
        }
        __syncthreads();
    }

    // warp softmax over g (lanes)
    float m = acc;
    #pragma unroll
    for (int off = 16; off > 0; off >>= 1)
        m = fmaxf(m, __shfl_xor_sync(0xffffffffu, m, off));
    float e = __expf(acc - m);
    float sum = e;
    #pragma unroll
    for (int off = 16; off > 0; off >>= 1)
        sum += __shfl_xor_sync(0xffffffffu, sum, off);
    att[(size_t)(b0 + bb) * (C_ * G_) + c * G_ + g] = e / sum;
}

// ---------------- K4b: pooled ----------------
__global__ void __launch_bounds__(256) pooled_kernel(
    const float* __restrict__ att, const float* __restrict__ gst_emb)
{
    int b0 = blockIdx.x * 8;
    int d = threadIdx.x;
    __shared__ float attS[8][C_ * G_];
    #pragma unroll
    for (int p = 0; p < 16; p++) {
        int idx = threadIdx.x + p * 256;
        attS[idx >> 9][idx & 511] = att[(size_t)b0 * 512 + idx];
    }
    __syncthreads();
    float acc[8];
    #pragma unroll
    for (int i = 0; i < 8; i++) acc[i] = 0.f;
    for (int cg = 0; cg < C_ * G_; cg++) {
        float e = gst_emb[(size_t)cg * D_ + d];
        #pragma unroll
        for (int i = 0; i < 8; i++) acc[i] = fmaf(attS[i][cg], e, acc[i]);
    }
    #pragma unroll
    for (int i = 0; i < 8; i++)
        g_pooled[(size_t)(b0 + i) * D_ + d] = acc[i] * (1.0f / C_);
}

// ---------------- K4c: out ----------------
__global__ void __launch_bounds__(256) out_kernel(
    const float* __restrict__ out_w, const float* __restrict__ out_b,
    float* __restrict__ outp)
{
    int b0 = blockIdx.x * 8;
    int o = threadIdx.x;
    __shared__ float ps[8][D_];
    #pragma unroll
    for (int p = 0; p < 8; p++) {
        int idx = threadIdx.x + p * 256;
        ps[idx >> 8][idx & 255] = g_pooled[(size_t)b0 * D_ + idx];
    }
    __syncthreads();
    float acc[8];
    #pragma unroll
    for (int i = 0; i < 8; i++) acc[i] = 0.f;
    const float* wrow = out_w + (size_t)o * D_;
    for (int dd = 0; dd < D_; dd += 4) {
        float4 w4 = *(const float4*)(wrow + dd);
        #pragma unroll
        for (int i = 0; i < 8; i++) {
            float a = acc[i];
            a = fmaf(ps[i][dd],     w4.x, a);
            a = fmaf(ps[i][dd + 1], w4.y, a);
            a = fmaf(ps[i][dd + 2], w4.z, a);
            a = fmaf(ps[i][dd + 3], w4.w, a);
            acc[i] = a;
        }
    }
    float bias = out_b[o];
    #pragma unroll
    for (int i = 0; i < 8; i++)
        outp[(size_t)(b0 + i) * O_ + o] = acc[i] + bias;
}

extern "C" void kernel_launch(void* const* d_in, const int* in_sizes, int n_in,
                              void* d_out, int out_size)
{
    const float* hidden  = (const float*)d_in[0];
    const float* gst_emb = (const float*)d_in[1];
    const float* attn_w  = (const float*)d_in[2];
    const float* attn_b  = (const float*)d_in[3];
    const float* v       = (const float*)d_in[4];
    const float* out_w   = (const float*)d_in[5];
    const float* out_b   = (const float*)d_in[6];
    float* out  = (float*)d_out;
    float* att  = out;                   // [B, C*G]
    float* outp = out + B_ * C_ * G_;    // [B, O]

    cudaFuncSetAttribute(gemm_mma_kernel,
                         cudaFuncAttributeMaxDynamicSharedMemorySize, GSMEM);

    convert_a_kernel     <<<128,  256>>>(hidden);
    convert_w_kernel     <<<8192, 256>>>(attn_w);
    ebias_kernel         <<<dim3(C_, 8), 256>>>(gst_emb, attn_w, attn_b);
    gemm_mma_kernel      <<<dim3(8, 2, C_), 256, GSMEM>>>();
    scores_softmax_kernel<<<dim3(C_, 32), 256>>>(v, att);
    pooled_kernel        <<<B_ / 8, 256>>>(att, gst_emb);
    out_kernel           <<<B_ / 8, 256>>>(out_w, out_b, outp);
}

// round 9
// speedup vs baseline: 1.1479x; 1.0671x over previous
#include <cuda_runtime.h>
#include <cuda_bf16.h>
#include <cstdint>

#define B_ 256
#define H_ 1024
#define D_ 256
#define C_ 16
#define G_ 32
#define O_ 256
#define HD_ 1280  // H + D

// ---------------- device-global scratch (no cudaMalloc allowed) ----------------
__device__ float g_hid[B_ * C_ * H_];      // [b][c][h]  = exp2(2.885 * hid_part)
__device__ float g_ebias[C_ * G_ * H_];    // [c][g][h]  = exp2(2.885 * (enc_part + bias))
__device__ float g_pooled[B_ * D_];        // [b][d]

// bf16 hi/lo split operands, plain row-major (k contiguous).
__device__ uint4 g_ah[B_ * H_ / 8];            // A hi  [m][k]   0.5 MB
__device__ uint4 g_al[B_ * H_ / 8];            // A lo
__device__ uint4 g_wh[C_ * H_ * H_ / 8];       // W hi  [c][n][k]  32 MB
__device__ uint4 g_wl[C_ * H_ * H_ / 8];       // W lo

// ---------------- helpers ----------------
__device__ __forceinline__ uint32_t smem_u32(const void* p) {
    uint32_t a;
    asm("{ .reg .u64 t; cvta.to.shared.u64 t, %1; cvt.u32.u64 %0, t; }"
        : "=r"(a) : "l"(p));
    return a;
}
__device__ __forceinline__ void cp16(uint32_t dst, const void* src) {
    asm volatile("cp.async.cg.shared.global [%0], [%1], 16;"
                 :: "r"(dst), "l"(src) : "memory");
}
__device__ __forceinline__ void ldsm4(uint32_t* r, uint32_t addr) {
    asm volatile("ldmatrix.sync.aligned.m8n8.x4.shared.b16 {%0,%1,%2,%3}, [%4];"
                 : "=r"(r[0]), "=r"(r[1]), "=r"(r[2]), "=r"(r[3]) : "r"(addr));
}
__device__ __forceinline__ void mma16816(float* d, const uint32_t* a, const uint32_t* b) {
    asm volatile(
        "mma.sync.aligned.m16n8k16.row.col.f32.bf16.bf16.f32 "
        "{%0,%1,%2,%3}, {%4,%5,%6,%7}, {%8,%9}, {%0,%1,%2,%3};"
        : "+f"(d[0]), "+f"(d[1]), "+f"(d[2]), "+f"(d[3])
        : "r"(a[0]), "r"(a[1]), "r"(a[2]), "r"(a[3]), "r"(b[0]), "r"(b[1]));
}
// exp2 via MUFU
__device__ __forceinline__ float ex2f(float x) {
    float r;
    asm("ex2.approx.f32 %0, %1;" : "=f"(r) : "f"(x));
    return r;
}
#define TANH_SCALE 2.8853900817779268f   // 2 * log2(e)

// packed fp32x2 (proven on this harness in R3: fma.rn.f32x2 only)
__device__ __forceinline__ unsigned long long pack2f(float x, float y) {
    unsigned long long r;
    asm("mov.b64 %0, {%1, %2};" : "=l"(r) : "f"(x), "f"(y));
    return r;
}
__device__ __forceinline__ void unpack2f(unsigned long long p, float& x, float& y) {
    asm("mov.b64 {%0, %1}, %2;" : "=f"(x), "=f"(y) : "l"(p));
}

__device__ __forceinline__ void split8(const float* xs, uint32_t* hw, uint32_t* lw) {
    #pragma unroll
    for (int i = 0; i < 4; i++) {
        __nv_bfloat16 h0 = __float2bfloat16(xs[2*i]);
        __nv_bfloat16 h1 = __float2bfloat16(xs[2*i+1]);
        __nv_bfloat16 l0 = __float2bfloat16(xs[2*i]   - __bfloat162float(h0));
        __nv_bfloat16 l1 = __float2bfloat16(xs[2*i+1] - __bfloat162float(h1));
        hw[i] = (uint32_t)__bfloat16_as_ushort(h0) | ((uint32_t)__bfloat16_as_ushort(h1) << 16);
        lw[i] = (uint32_t)__bfloat16_as_ushort(l0) | ((uint32_t)__bfloat16_as_ushort(l1) << 16);
    }
}

// ---------------- K0a: split hidden -> bf16 hi/lo ----------------
__global__ void __launch_bounds__(256) convert_a_kernel(const float* __restrict__ hidden)
{
    int idx = blockIdx.x * 256 + threadIdx.x;   // 32768
    int b = idx >> 7, j = idx & 127;
    const float4* s = (const float4*)(hidden + (size_t)b * H_ + j * 8);
    float4 x0 = s[0], x1 = s[1];
    float xs[8] = {x0.x, x0.y, x0.z, x0.w, x1.x, x1.y, x1.z, x1.w};
    uint32_t hw[4], lw[4];
    split8(xs, hw, lw);
    g_ah[b * 128 + j] = make_uint4(hw[0], hw[1], hw[2], hw[3]);
    g_al[b * 128 + j] = make_uint4(lw[0], lw[1], lw[2], lw[3]);
}

// ---------------- K0b: split w_hid -> bf16 hi/lo ----------------
__global__ void __launch_bounds__(256) convert_w_kernel(const float* __restrict__ attn_w)
{
    int idx = blockIdx.x * 256 + threadIdx.x;   // 2,097,152
    int j = idx & 127;
    int o = (idx >> 7) & 1023;
    int c = idx >> 17;
    const float4* s = (const float4*)(attn_w + ((size_t)c * H_ + o) * HD_ + j * 8);
    float4 x0 = s[0], x1 = s[1];
    float xs[8] = {x0.x, x0.y, x0.z, x0.w, x1.x, x1.y, x1.z, x1.w};
    uint32_t hw[4], lw[4];
    split8(xs, hw, lw);
    size_t u = (size_t)c * 131072 + (size_t)o * 128 + j;
    g_wh[u] = make_uint4(hw[0], hw[1], hw[2], hw[3]);
    g_wl[u] = make_uint4(lw[0], lw[1], lw[2], lw[3]);
}

// ---------------- K1: ebias -> exp2 domain ----------------
__global__ void __launch_bounds__(256) ebias_kernel(
    const float* __restrict__ gst_emb, const float* __restrict__ attn_w,
    const float* __restrict__ attn_b)
{
    int c = blockIdx.x;
    int o = blockIdx.y * 128 + (threadIdx.x & 127);
    int gbase = (threadIdx.x >> 7) * 16;
    __shared__ float gs[G_][D_];
    const float4* src = (const float4*)(gst_emb + (size_t)c * G_ * D_);
    for (int i = threadIdx.x; i < G_ * D_ / 4; i += 256)
        ((float4*)gs)[i] = src[i];
    __syncthreads();

    float acc[16];
    #pragma unroll
    for (int g = 0; g < 16; g++) acc[g] = 0.f;

    const float* wrow = attn_w + (size_t)c * H_ * HD_ + (size_t)o * HD_ + H_;
    for (int d = 0; d < D_; d += 4) {
        float4 w4 = *(const float4*)(wrow + d);
        #pragma unroll
        for (int g = 0; g < 16; g++) {
            float a = acc[g];
            a = fmaf(gs[gbase + g][d],     w4.x, a);
            a = fmaf(gs[gbase + g][d + 1], w4.y, a);
            a = fmaf(gs[gbase + g][d + 2], w4.z, a);
            a = fmaf(gs[gbase + g][d + 3], w4.w, a);
            acc[g] = a;
        }
    }
    float bias = attn_b[c * H_ + o];
    #pragma unroll
    for (int g = 0; g < 16; g++)
        g_ebias[(size_t)c * G_ * H_ + (size_t)(gbase + g) * H_ + o] =
            ex2f((acc[g] + bias) * TANH_SCALE);
}

// ---------------- K2: hid_part GEMM via mma.sync bf16 hi/lo ----------------
#define LDROW 80
#define TILEB (128 * LDROW)
#define STAGEB (4 * TILEB)
#define GSMEM (2 * STAGEB)          // 81920
#define NKC 32

__global__ void __launch_bounds__(256) gemm_mma_kernel()
{
    extern __shared__ char smem[];
    uint32_t sb = smem_u32(smem);
    int t = threadIdx.x, w = t >> 5, l = t & 31;
    int wm = w & 1, wn = w >> 1;
    int bn0 = blockIdx.x * 128, bm0 = blockIdx.y * 128, c = blockIdx.z;

    const uint4* pAh = g_ah + (size_t)bm0 * 128;
    const uint4* pAl = g_al + (size_t)bm0 * 128;
    const uint4* pBh = g_wh + (size_t)c * 131072 + (size_t)bn0 * 128;
    const uint4* pBl = g_wl + (size_t)c * 131072 + (size_t)bn0 * 128;

    int row = t >> 2, q = t & 3;
    uint32_t cpdst = (uint32_t)(row * LDROW + q * 16);

    float acc[4][4][4];
    #pragma unroll
    for (int i = 0; i < 4; i++)
        #pragma unroll
        for (int j = 0; j < 4; j++)
            #pragma unroll
            for (int k = 0; k < 4; k++) acc[i][j][k] = 0.f;

    auto stage_load = [&](int kc, int buf) {
        uint32_t base = sb + buf * STAGEB;
        #pragma unroll
        for (int h = 0; h < 2; h++) {
            int r = row + h * 64;
            int su = r * 128 + kc * 4 + q;
            uint32_t d = base + cpdst + h * 64 * LDROW;
            cp16(d,              pAh + su);
            cp16(d + TILEB,      pAl + su);
            cp16(d + 2 * TILEB,  pBh + su);
            cp16(d + 3 * TILEB,  pBl + su);
        }
        asm volatile("cp.async.commit_group;" ::: "memory");
    };

    stage_load(0, 0);

    uint32_t arow_off = (uint32_t)((l & 15) * LDROW + (l >> 4) * 16);
    uint32_t brow_off = (uint32_t)((((l & 7) + ((l >> 4) << 3)) * LDROW) + ((l >> 3) & 1) * 16);

    for (int kc = 0; kc < NKC; kc++) {
        int cur = kc & 1;
        if (kc + 1 < NKC) {
            stage_load(kc + 1, cur ^ 1);
            asm volatile("cp.async.wait_group 1;" ::: "memory");
        } else {
            asm volatile("cp.async.wait_group 0;" ::: "memory");
        }
        __syncthreads();

        uint32_t base = sb + cur * STAGEB;
        #pragma unroll
        for (int kk = 0; kk < 2; kk++) {
            uint32_t kkb = kk * 32;
            uint32_t aH[4][4], aL[4][4], bH[2][4], bL[2][4];
            #pragma unroll
            for (int mt = 0; mt < 4; mt++) {
                uint32_t ad = base + (uint32_t)((wm * 64 + mt * 16) * LDROW) + kkb + arow_off;
                ldsm4(aH[mt], ad);
                ldsm4(aL[mt], ad + TILEB);
            }
            #pragma unroll
            for (int p = 0; p < 2; p++) {
                uint32_t bd = base + 2 * TILEB +
                              (uint32_t)((wn * 32 + p * 16) * LDROW) + kkb + brow_off;
                ldsm4(bH[p], bd);
                ldsm4(bL[p], bd + TILEB);
            }
            #pragma unroll
            for (int mt = 0; mt < 4; mt++)
                #pragma unroll
                for (int p = 0; p < 2; p++)
                    #pragma unroll
                    for (int hf = 0; hf < 2; hf++) {
                        int nt = p * 2 + hf;
                        mma16816(acc[mt][nt], aH[mt], &bH[p][hf * 2]);
                        mma16816(acc[mt][nt], aH[mt], &bL[p][hf * 2]);
                        mma16816(acc[mt][nt], aL[mt], &bH[p][hf * 2]);
                    }
        }
        __syncthreads();
    }

    // epilogue: Eh = exp2(2.885 * acc) -> g_hid[b][c][h]
    #pragma unroll
    for (int mt = 0; mt < 4; mt++) {
        int m0 = bm0 + wm * 64 + mt * 16 + (l >> 2);
        #pragma unroll
        for (int nt = 0; nt < 4; nt++) {
            int col = bn0 + wn * 32 + nt * 8 + (l & 3) * 2;
            float* d0 = g_hid + (size_t)m0 * (C_ * H_) + (size_t)c * H_ + col;
            *(float2*)d0 = make_float2(ex2f(acc[mt][nt][0] * TANH_SCALE),
                                       ex2f(acc[mt][nt][1] * TANH_SCALE));
            *(float2*)(d0 + (size_t)8 * C_ * H_) =
                make_float2(ex2f(acc[mt][nt][2] * TANH_SCALE),
                            ex2f(acc[mt][nt][3] * TANH_SCALE));
        }
    }
}

// ---------------- K3: fused scores + softmax, packed f32x2 inner loop ----------------
// tanh(x) = 1 - 2/(1 + Eh*Ee); per PAIR of h: 1 packed FMA (Eh*Ee+1), 2 MUFU rcp,
// 1 packed FMA (1-2r), 1 packed FMA (v*t+acc) -> 5 instr/element incl. 3 LDS.64.
__global__ void __launch_bounds__(256) scores_softmax_kernel(
    const float* __restrict__ v, float* __restrict__ att)
{
    int c = blockIdx.x;
    int b0 = blockIdx.y * 8;
    __shared__ float ehS[8][130];    // even stride: LDS.64-aligned, conflict-free
    __shared__ float eeS[32][130];
    __shared__ float vS[128];
    int t = threadIdx.x;
    int g = t & 31, bb = t >> 5;

    unsigned long long acc2 = pack2f(0.f, 0.f);
    const unsigned long long ONE2 = pack2f(1.f, 1.f);
    const unsigned long long NEG2 = pack2f(-2.f, -2.f);

    for (int hc = 0; hc < H_; hc += 128) {
        #pragma unroll
        for (int p = 0; p < 2; p++) {   // Eh tile: 8 rows x 128 (512 float2)
            int idx = t + p * 256;
            int r = idx >> 6, j2 = idx & 63;
            float2 hv = *(const float2*)(g_hid + (size_t)(b0 + r) * (C_ * H_) +
                                         (size_t)c * H_ + hc + j2 * 2);
            *(float2*)&ehS[r][j2 * 2] = hv;
        }
        #pragma unroll
        for (int p = 0; p < 8; p++) {   // Ee tile: 32 rows x 128 (2048 float2)
            int idx = t + p * 256;
            int r = idx >> 6, j2 = idx & 63;
            float2 ev = *(const float2*)(g_ebias + (size_t)c * (G_ * H_) +
                                         (size_t)r * H_ + hc + j2 * 2);
            *(float2*)&eeS[r][j2 * 2] = ev;
        }
        if (t < 64) {
            float2 vv = *(const float2*)(v + (size_t)c * H_ + hc + t * 2);
            *(float2*)&vS[t * 2] = vv;
        }
        __syncthreads();

        #pragma unroll 8
        for (int j2 = 0; j2 < 64; j2++) {
            unsigned long long eh2 = *(const unsigned long long*)&ehS[bb][j2 * 2];
            unsigned long long ee2 = *(const unsigned long long*)&eeS[g][j2 * 2];
            unsigned long long v2  = *(const unsigned long long*)&vS[j2 * 2];
            unsigned long long d2, r2, t2;
            asm("fma.rn.f32x2 %0, %1, %2, %3;" : "=l"(d2) : "l"(eh2), "l"(ee2), "l"(ONE2));
            float d0, d1, r0, r1;
            unpack2f(d2, d0, d1);
            asm("rcp.approx.f32 %0, %1;" : "=f"(r0) : "f"(d0));
            asm("rcp.approx.f32 %0, %1;" : "=f"(r1) : "f"(d1));
            r2 = pack2f(r0, r1);
            asm("fma.rn.f32x2 %0, %1, %2, %3;" : "=l"(t2) : "l"(NEG2), "l"(r2), "l"(ONE2));
            asm("fma.rn.f32x2 %0, %1, %2, %0;" : "+l"(acc2) : "l"(v2), "l"(t2));
        }
        __syncthreads();
    }

    float a0, a1;
    unpack2f(acc2, a0, a1);
    float acc = a0 + a1;

    // warp softmax over g (lanes)
    float m = acc;
    #pragma unroll
    for (int off = 16; off > 0; off >>= 1)
        m = fmaxf(m, __shfl_xor_sync(0xffffffffu, m, off));
    float e = __expf(acc - m);
    float sum = e;
    #pragma unroll
    for (int off = 16; off > 0; off >>= 1)
        sum += __shfl_xor_sync(0xffffffffu, sum, off);
    att[(size_t)(b0 + bb) * (C_ * G_) + c * G_ + g] = e / sum;
}

// ---------------- K4b: pooled ----------------
__global__ void __launch_bounds__(256) pooled_kernel(
    const float* __restrict__ att, const float* __restrict__ gst_emb)
{
    int b0 = blockIdx.x * 8;
    int d = threadIdx.x;
    __shared__ float attS[8][C_ * G_];
    #pragma unroll
    for (int p = 0; p < 16; p++) {
        int idx = threadIdx.x + p * 256;
        attS[idx >> 9][idx & 511] = att[(size_t)b0 * 512 + idx];
    }
    __syncthreads();
    float acc[8];
    #pragma unroll
    for (int i = 0; i < 8; i++) acc[i] = 0.f;
    for (int cg = 0; cg < C_ * G_; cg++) {
        float e = gst_emb[(size_t)cg * D_ + d];
        #pragma unroll
        for (int i = 0; i < 8; i++) acc[i] = fmaf(attS[i][cg], e, acc[i]);
    }
    #pragma unroll
    for (int i = 0; i < 8; i++)
        g_pooled[(size_t)(b0 + i) * D_ + d] = acc[i] * (1.0f / C_);
}

// ---------------- K4c: out ----------------
__global__ void __launch_bounds__(256) out_kernel(
    const float* __restrict__ out_w, const float* __restrict__ out_b,
    float* __restrict__ outp)
{
    int b0 = blockIdx.x * 8;
    int o = threadIdx.x;
    __shared__ float ps[8][D_];
    #pragma unroll
    for (int p = 0; p < 8; p++) {
        int idx = threadIdx.x + p * 256;
        ps[idx >> 8][idx & 255] = g_pooled[(size_t)b0 * D_ + idx];
    }
    __syncthreads();
    float acc[8];
    #pragma unroll
    for (int i = 0; i < 8; i++) acc[i] = 0.f;
    const float* wrow = out_w + (size_t)o * D_;
    for (int dd = 0; dd < D_; dd += 4) {
        float4 w4 = *(const float4*)(wrow + dd);
        #pragma unroll
        for (int i = 0; i < 8; i++) {
            float a = acc[i];
            a = fmaf(ps[i][dd],     w4.x, a);
            a = fmaf(ps[i][dd + 1], w4.y, a);
            a = fmaf(ps[i][dd + 2], w4.z, a);
            a = fmaf(ps[i][dd + 3], w4.w, a);
            acc[i] = a;
        }
    }
    float bias = out_b[o];
    #pragma unroll
    for (int i = 0; i < 8; i++)
        outp[(size_t)(b0 + i) * O_ + o] = acc[i] + bias;
}

extern "C" void kernel_launch(void* const* d_in, const int* in_sizes, int n_in,
                              void* d_out, int out_size)
{
    const float* hidden  = (const float*)d_in[0];
    const float* gst_emb = (const float*)d_in[1];
    const float* attn_w  = (const float*)d_in[2];
    const float* attn_b  = (const float*)d_in[3];
    const float* v       = (const float*)d_in[4];
    const float* out_w   = (const float*)d_in[5];
    const float* out_b   = (const float*)d_in[6];
    float* out  = (float*)d_out;
    float* att  = out;                   // [B, C*G]
    float* outp = out + B_ * C_ * G_;    // [B, O]

    cudaFuncSetAttribute(gemm_mma_kernel,
                         cudaFuncAttributeMaxDynamicSharedMemorySize, GSMEM);

    convert_a_kernel     <<<128,  256>>>(hidden);
    convert_w_kernel     <<<8192, 256>>>(attn_w);
    ebias_kernel         <<<dim3(C_, 8), 256>>>(gst_emb, attn_w, attn_b);
    gemm_mma_kernel      <<<dim3(8, 2, C_), 256, GSMEM>>>();
    scores_softmax_kernel<<<dim3(C_, 32), 256>>>(v, att);
    pooled_kernel        <<<B_ / 8, 256>>>(att, gst_emb);
    out_kernel           <<<B_ / 8, 256>>>(out_w, out_b, outp);
}

// round 10
// speedup vs baseline: 1.1754x; 1.0239x over previous
#include <cuda_runtime.h>
#include <cuda_bf16.h>
#include <cstdint>

#define B_ 256
#define H_ 1024
#define D_ 256
#define C_ 16
#define G_ 32
#define O_ 256
#define HD_ 1280  // H + D

// ---------------- device-global scratch (no cudaMalloc allowed) ----------------
__device__ float g_hid[B_ * C_ * H_];      // [b][c][h]  = exp2(2.885 * hid_part)
__device__ float g_ebias[C_ * G_ * H_];    // [c][g][h]  = exp2(2.885 * (enc_part + bias))
__device__ float g_pooled[B_ * D_];        // [b][d]
__device__ float g_vsum[C_];               // [c] = sum_h v[c][h]

// bf16 hi/lo split operands, plain row-major (k contiguous).
__device__ uint4 g_ah[B_ * H_ / 8];            // A hi  [m][k]   0.5 MB
__device__ uint4 g_al[B_ * H_ / 8];            // A lo
__device__ uint4 g_wh[C_ * H_ * H_ / 8];       // W hi  [c][n][k]  32 MB
__device__ uint4 g_wl[C_ * H_ * H_ / 8];       // W lo

// ---------------- helpers ----------------
__device__ __forceinline__ uint32_t smem_u32(const void* p) {
    uint32_t a;
    asm("{ .reg .u64 t; cvta.to.shared.u64 t, %1; cvt.u32.u64 %0, t; }"
        : "=r"(a) : "l"(p));
    return a;
}
__device__ __forceinline__ void cp16(uint32_t dst, const void* src) {
    asm volatile("cp.async.cg.shared.global [%0], [%1], 16;"
                 :: "r"(dst), "l"(src) : "memory");
}
__device__ __forceinline__ void ldsm4(uint32_t* r, uint32_t addr) {
    asm volatile("ldmatrix.sync.aligned.m8n8.x4.shared.b16 {%0,%1,%2,%3}, [%4];"
                 : "=r"(r[0]), "=r"(r[1]), "=r"(r[2]), "=r"(r[3]) : "r"(addr));
}
__device__ __forceinline__ void mma16816(float* d, const uint32_t* a, const uint32_t* b) {
    asm volatile(
        "mma.sync.aligned.m16n8k16.row.col.f32.bf16.bf16.f32 "
        "{%0,%1,%2,%3}, {%4,%5,%6,%7}, {%8,%9}, {%0,%1,%2,%3};"
        : "+f"(d[0]), "+f"(d[1]), "+f"(d[2]), "+f"(d[3])
        : "r"(a[0]), "r"(a[1]), "r"(a[2]), "r"(a[3]), "r"(b[0]), "r"(b[1]));
}
// exp2 via MUFU
__device__ __forceinline__ float ex2f(float x) {
    float r;
    asm("ex2.approx.f32 %0, %1;" : "=f"(r) : "f"(x));
    return r;
}
#define TANH_SCALE 2.8853900817779268f   // 2 * log2(e)

// packed fp32x2
__device__ __forceinline__ unsigned long long pack2f(float x, float y) {
    unsigned long long r;
    asm("mov.b64 %0, {%1, %2};" : "=l"(r) : "f"(x), "f"(y));
    return r;
}
__device__ __forceinline__ void unpack2f(unsigned long long p, float& x, float& y) {
    asm("mov.b64 {%0, %1}, %2;" : "=f"(x), "=f"(y) : "l"(p));
}

__device__ __forceinline__ void split8(const float* xs, uint32_t* hw, uint32_t* lw) {
    #pragma unroll
    for (int i = 0; i < 4; i++) {
        __nv_bfloat16 h0 = __float2bfloat16(xs[2*i]);
        __nv_bfloat16 h1 = __float2bfloat16(xs[2*i+1]);
        __nv_bfloat16 l0 = __float2bfloat16(xs[2*i]   - __bfloat162float(h0));
        __nv_bfloat16 l1 = __float2bfloat16(xs[2*i+1] - __bfloat162float(h1));
        hw[i] = (uint32_t)__bfloat16_as_ushort(h0) | ((uint32_t)__bfloat16_as_ushort(h1) << 16);
        lw[i] = (uint32_t)__bfloat16_as_ushort(l0) | ((uint32_t)__bfloat16_as_ushort(l1) << 16);
    }
}

// ---------------- K0a: split hidden -> bf16 hi/lo ----------------
__global__ void __launch_bounds__(256) convert_a_kernel(const float* __restrict__ hidden)
{
    int idx = blockIdx.x * 256 + threadIdx.x;   // 32768
    int b = idx >> 7, j = idx & 127;
    const float4* s = (const float4*)(hidden + (size_t)b * H_ + j * 8);
    float4 x0 = s[0], x1 = s[1];
    float xs[8] = {x0.x, x0.y, x0.z, x0.w, x1.x, x1.y, x1.z, x1.w};
    uint32_t hw[4], lw[4];
    split8(xs, hw, lw);
    g_ah[b * 128 + j] = make_uint4(hw[0], hw[1], hw[2], hw[3]);
    g_al[b * 128 + j] = make_uint4(lw[0], lw[1], lw[2], lw[3]);
}

// ---------------- K0v: per-c sum of v ----------------
__global__ void __launch_bounds__(256) vsum_kernel(const float* __restrict__ v)
{
    int c = blockIdx.x;
    int t = threadIdx.x;
    float s = 0.f;
    #pragma unroll
    for (int p = 0; p < 4; p++) s += v[(size_t)c * H_ + t + p * 256];
    #pragma unroll
    for (int off = 16; off > 0; off >>= 1)
        s += __shfl_xor_sync(0xffffffffu, s, off);
    __shared__ float ws[8];
    if ((t & 31) == 0) ws[t >> 5] = s;
    __syncthreads();
    if (t == 0) {
        float tot = 0.f;
        #pragma unroll
        for (int i = 0; i < 8; i++) tot += ws[i];
        g_vsum[c] = tot;
    }
}

// ---------------- K0b: split w_hid -> bf16 hi/lo ----------------
__global__ void __launch_bounds__(256) convert_w_kernel(const float* __restrict__ attn_w)
{
    int idx = blockIdx.x * 256 + threadIdx.x;   // 2,097,152
    int j = idx & 127;
    int o = (idx >> 7) & 1023;
    int c = idx >> 17;
    const float4* s = (const float4*)(attn_w + ((size_t)c * H_ + o) * HD_ + j * 8);
    float4 x0 = s[0], x1 = s[1];
    float xs[8] = {x0.x, x0.y, x0.z, x0.w, x1.x, x1.y, x1.z, x1.w};
    uint32_t hw[4], lw[4];
    split8(xs, hw, lw);
    size_t u = (size_t)c * 131072 + (size_t)o * 128 + j;
    g_wh[u] = make_uint4(hw[0], hw[1], hw[2], hw[3]);
    g_wl[u] = make_uint4(lw[0], lw[1], lw[2], lw[3]);
}

// ---------------- K1: ebias -> exp2 domain ----------------
__global__ void __launch_bounds__(256) ebias_kernel(
    const float* __restrict__ gst_emb, const float* __restrict__ attn_w,
    const float* __restrict__ attn_b)
{
    int c = blockIdx.x;
    int o = blockIdx.y * 128 + (threadIdx.x & 127);
    int gbase = (threadIdx.x >> 7) * 16;
    __shared__ float gs[G_][D_];
    const float4* src = (const float4*)(gst_emb + (size_t)c * G_ * D_);
    for (int i = threadIdx.x; i < G_ * D_ / 4; i += 256)
        ((float4*)gs)[i] = src[i];
    __syncthreads();

    float acc[16];
    #pragma unroll
    for (int g = 0; g < 16; g++) acc[g] = 0.f;

    const float* wrow = attn_w + (size_t)c * H_ * HD_ + (size_t)o * HD_ + H_;
    for (int d = 0; d < D_; d += 4) {
        float4 w4 = *(const float4*)(wrow + d);
        #pragma unroll
        for (int g = 0; g < 16; g++) {
            float a = acc[g];
            a = fmaf(gs[gbase + g][d],     w4.x, a);
            a = fmaf(gs[gbase + g][d + 1], w4.y, a);
            a = fmaf(gs[gbase + g][d + 2], w4.z, a);
            a = fmaf(gs[gbase + g][d + 3], w4.w, a);
            acc[g] = a;
        }
    }
    float bias = attn_b[c * H_ + o];
    #pragma unroll
    for (int g = 0; g < 16; g++)
        g_ebias[(size_t)c * G_ * H_ + (size_t)(gbase + g) * H_ + o] =
            ex2f((acc[g] + bias) * TANH_SCALE);
}

// ---------------- K2: hid_part GEMM via mma.sync bf16 hi/lo ----------------
#define LDROW 80
#define TILEB (128 * LDROW)
#define STAGEB (4 * TILEB)
#define GSMEM (2 * STAGEB)          // 81920
#define NKC 32

__global__ void __launch_bounds__(256) gemm_mma_kernel()
{
    extern __shared__ char smem[];
    uint32_t sb = smem_u32(smem);
    int t = threadIdx.x, w = t >> 5, l = t & 31;
    int wm = w & 1, wn = w >> 1;
    int bn0 = blockIdx.x * 128, bm0 = blockIdx.y * 128, c = blockIdx.z;

    const uint4* pAh = g_ah + (size_t)bm0 * 128;
    const uint4* pAl = g_al + (size_t)bm0 * 128;
    const uint4* pBh = g_wh + (size_t)c * 131072 + (size_t)bn0 * 128;
    const uint4* pBl = g_wl + (size_t)c * 131072 + (size_t)bn0 * 128;

    int row = t >> 2, q = t & 3;
    uint32_t cpdst = (uint32_t)(row * LDROW + q * 16);

    float acc[4][4][4];
    #pragma unroll
    for (int i = 0; i < 4; i++)
        #pragma unroll
        for (int j = 0; j < 4; j++)
            #pragma unroll
            for (int k = 0; k < 4; k++) acc[i][j][k] = 0.f;

    auto stage_load = [&](int kc, int buf) {
        uint32_t base = sb + buf * STAGEB;
        #pragma unroll
        for (int h = 0; h < 2; h++) {
            int r = row + h * 64;
            int su = r * 128 + kc * 4 + q;
            uint32_t d = base + cpdst + h * 64 * LDROW;
            cp16(d,              pAh + su);
            cp16(d + TILEB,      pAl + su);
            cp16(d + 2 * TILEB,  pBh + su);
            cp16(d + 3 * TILEB,  pBl + su);
        }
        asm volatile("cp.async.commit_group;" ::: "memory");
    };

    stage_load(0, 0);

    uint32_t arow_off = (uint32_t)((l & 15) * LDROW + (l >> 4) * 16);
    uint32_t brow_off = (uint32_t)((((l & 7) + ((l >> 4) << 3)) * LDROW) + ((l >> 3) & 1) * 16);

    for (int kc = 0; kc < NKC; kc++) {
        int cur = kc & 1;
        if (kc + 1 < NKC) {
            stage_load(kc + 1, cur ^ 1);
            asm volatile("cp.async.wait_group 1;" ::: "memory");
        } else {
            asm volatile("cp.async.wait_group 0;" ::: "memory");
        }
        __syncthreads();

        uint32_t base = sb + cur * STAGEB;
        #pragma unroll
        for (int kk = 0; kk < 2; kk++) {
            uint32_t kkb = kk * 32;
            uint32_t aH[4][4], aL[4][4], bH[2][4], bL[2][4];
            #pragma unroll
            for (int mt = 0; mt < 4; mt++) {
                uint32_t ad = base + (uint32_t)((wm * 64 + mt * 16) * LDROW) + kkb + arow_off;
                ldsm4(aH[mt], ad);
                ldsm4(aL[mt], ad + TILEB);
            }
            #pragma unroll
            for (int p = 0; p < 2; p++) {
                uint32_t bd = base + 2 * TILEB +
                              (uint32_t)((wn * 32 + p * 16) * LDROW) + kkb + brow_off;
                ldsm4(bH[p], bd);
                ldsm4(bL[p], bd + TILEB);
            }
            #pragma unroll
            for (int mt = 0; mt < 4; mt++)
                #pragma unroll
                for (int p = 0; p < 2; p++)
                    #pragma unroll
                    for (int hf = 0; hf < 2; hf++) {
                        int nt = p * 2 + hf;
                        mma16816(acc[mt][nt], aH[mt], &bH[p][hf * 2]);
                        mma16816(acc[mt][nt], aH[mt], &bL[p][hf * 2]);
                        mma16816(acc[mt][nt], aL[mt], &bH[p][hf * 2]);
                    }
        }
        __syncthreads();
    }

    // epilogue: Eh = exp2(2.885 * acc) -> g_hid[b][c][h]
    #pragma unroll
    for (int mt = 0; mt < 4; mt++) {
        int m0 = bm0 + wm * 64 + mt * 16 + (l >> 2);
        #pragma unroll
        for (int nt = 0; nt < 4; nt++) {
            int col = bn0 + wn * 32 + nt * 8 + (l & 3) * 2;
            float* d0 = g_hid + (size_t)m0 * (C_ * H_) + (size_t)c * H_ + col;
            *(float2*)d0 = make_float2(ex2f(acc[mt][nt][0] * TANH_SCALE),
                                       ex2f(acc[mt][nt][1] * TANH_SCALE));
            *(float2*)(d0 + (size_t)8 * C_ * H_) =
                make_float2(ex2f(acc[mt][nt][2] * TANH_SCALE),
                            ex2f(acc[mt][nt][3] * TANH_SCALE));
        }
    }
}

// ---------------- K3: fused scores + softmax, 2 batch rows per thread ----------------
// score = Vsum + sum_j (-2 v_j) * rcp(1 + Eh*Ee).  Per 2 j x 2 b (4 elements):
// 4 LDS.64 + 2 FMA2 + 4 MUFU + 2 FMA2.  ee (per-lane) loaded once per 2 b.
__global__ void __launch_bounds__(256) scores_softmax_kernel(
    const float* __restrict__ v, float* __restrict__ att)
{
    int c = blockIdx.x;
    int b0 = blockIdx.y * 16;
    __shared__ float ehS[16][130];
    __shared__ float eeS[32][130];
    __shared__ float w2S[128];       // -2 * v
    int t = threadIdx.x;
    int g = t & 31;
    int bbA = (t >> 5) * 2;          // warp-uniform pair of b rows

    unsigned long long accA = pack2f(0.f, 0.f);
    unsigned long long accB = pack2f(0.f, 0.f);
    const unsigned long long ONE2 = pack2f(1.f, 1.f);

    for (int hc = 0; hc < H_; hc += 128) {
        #pragma unroll
        for (int p = 0; p < 4; p++) {   // Eh tile: 16 rows x 128 (1024 float2)
            int idx = t + p * 256;
            int r = idx >> 6, j2 = idx & 63;
            float2 hv = *(const float2*)(g_hid + (size_t)(b0 + r) * (C_ * H_) +
                                         (size_t)c * H_ + hc + j2 * 2);
            *(float2*)&ehS[r][j2 * 2] = hv;
        }
        #pragma unroll
        for (int p = 0; p < 8; p++) {   // Ee tile: 32 rows x 128 (2048 float2)
            int idx = t + p * 256;
            int r = idx >> 6, j2 = idx & 63;
            float2 ev = *(const float2*)(g_ebias + (size_t)c * (G_ * H_) +
                                         (size_t)r * H_ + hc + j2 * 2);
            *(float2*)&eeS[r][j2 * 2] = ev;
        }
        if (t < 64) {
            float2 vv = *(const float2*)(v + (size_t)c * H_ + hc + t * 2);
            *(float2*)&w2S[t * 2] = make_float2(-2.f * vv.x, -2.f * vv.y);
        }
        __syncthreads();

        #pragma unroll 8
        for (int j2 = 0; j2 < 64; j2++) {
            unsigned long long ee2 = *(const unsigned long long*)&eeS[g][j2 * 2];
            unsigned long long ehA = *(const unsigned long long*)&ehS[bbA][j2 * 2];
            unsigned long long ehB = *(const unsigned long long*)&ehS[bbA + 1][j2 * 2];
            unsigned long long w2  = *(const unsigned long long*)&w2S[j2 * 2];
            unsigned long long dA, dB;
            asm("fma.rn.f32x2 %0, %1, %2, %3;" : "=l"(dA) : "l"(ehA), "l"(ee2), "l"(ONE2));
            asm("fma.rn.f32x2 %0, %1, %2, %3;" : "=l"(dB) : "l"(ehB), "l"(ee2), "l"(ONE2));
            float a0, a1, b0f, b1f, ra0, ra1, rb0, rb1;
            unpack2f(dA, a0, a1);
            unpack2f(dB, b0f, b1f);
            asm("rcp.approx.f32 %0, %1;" : "=f"(ra0) : "f"(a0));
            asm("rcp.approx.f32 %0, %1;" : "=f"(ra1) : "f"(a1));
            asm("rcp.approx.f32 %0, %1;" : "=f"(rb0) : "f"(b0f));
            asm("rcp.approx.f32 %0, %1;" : "=f"(rb1) : "f"(b1f));
            unsigned long long rA = pack2f(ra0, ra1);
            unsigned long long rB = pack2f(rb0, rb1);
            asm("fma.rn.f32x2 %0, %1, %2, %0;" : "+l"(accA) : "l"(w2), "l"(rA));
            asm("fma.rn.f32x2 %0, %1, %2, %0;" : "+l"(accB) : "l"(w2), "l"(rB));
        }
        __syncthreads();
    }

    float vs = g_vsum[c];
    float xA0, xA1, xB0, xB1;
    unpack2f(accA, xA0, xA1);
    unpack2f(accB, xB0, xB1);
    float sA = vs + xA0 + xA1;
    float sB = vs + xB0 + xB1;

    // warp softmax over g (lanes) for both b rows
    float mA = sA, mB = sB;
    #pragma unroll
    for (int off = 16; off > 0; off >>= 1) {
        mA = fmaxf(mA, __shfl_xor_sync(0xffffffffu, mA, off));
        mB = fmaxf(mB, __shfl_xor_sync(0xffffffffu, mB, off));
    }
    float eA = __expf(sA - mA), eB = __expf(sB - mB);
    float suA = eA, suB = eB;
    #pragma unroll
    for (int off = 16; off > 0; off >>= 1) {
        suA += __shfl_xor_sync(0xffffffffu, suA, off);
        suB += __shfl_xor_sync(0xffffffffu, suB, off);
    }
    att[(size_t)(b0 + bbA)     * (C_ * G_) + c * G_ + g] = eA / suA;
    att[(size_t)(b0 + bbA + 1) * (C_ * G_) + c * G_ + g] = eB / suB;
}

// ---------------- K4b: pooled (grid 64, 4 b per block, unrolled LDG) ----------------
__global__ void __launch_bounds__(256) pooled_kernel(
    const float* __restrict__ att, const float* __restrict__ gst_emb)
{
    int b0 = blockIdx.x * 4;
    int d = threadIdx.x;
    __shared__ float attS[4][C_ * G_];
    #pragma unroll
    for (int p = 0; p < 8; p++) {
        int idx = threadIdx.x + p * 256;
        attS[idx >> 9][idx & 511] = att[(size_t)b0 * 512 + idx];
    }
    __syncthreads();
    float acc[4];
    #pragma unroll
    for (int i = 0; i < 4; i++) acc[i] = 0.f;
    #pragma unroll 4
    for (int cg = 0; cg < C_ * G_; cg++) {
        float e = gst_emb[(size_t)cg * D_ + d];
        #pragma unroll
        for (int i = 0; i < 4; i++) acc[i] = fmaf(attS[i][cg], e, acc[i]);
    }
    #pragma unroll
    for (int i = 0; i < 4; i++)
        g_pooled[(size_t)(b0 + i) * D_ + d] = acc[i] * (1.0f / C_);
}

// ---------------- K4c: out ----------------
__global__ void __launch_bounds__(256) out_kernel(
    const float* __restrict__ out_w, const float* __restrict__ out_b,
    float* __restrict__ outp)
{
    int b0 = blockIdx.x * 8;
    int o = threadIdx.x;
    __shared__ float ps[8][D_];
    #pragma unroll
    for (int p = 0; p < 8; p++) {
        int idx = threadIdx.x + p * 256;
        ps[idx >> 8][idx & 255] = g_pooled[(size_t)b0 * D_ + idx];
    }
    __syncthreads();
    float acc[8];
    #pragma unroll
    for (int i = 0; i < 8; i++) acc[i] = 0.f;
    const float* wrow = out_w + (size_t)o * D_;
    for (int dd = 0; dd < D_; dd += 4) {
        float4 w4 = *(const float4*)(wrow + dd);
        #pragma unroll
        for (int i = 0; i < 8; i++) {
            float a = acc[i];
            a = fmaf(ps[i][dd],     w4.x, a);
            a = fmaf(ps[i][dd + 1], w4.y, a);
            a = fmaf(ps[i][dd + 2], w4.z, a);
            a = fmaf(ps[i][dd + 3], w4.w, a);
            acc[i] = a;
        }
    }
    float bias = out_b[o];
    #pragma unroll
    for (int i = 0; i < 8; i++)
        outp[(size_t)(b0 + i) * O_ + o] = acc[i] + bias;
}

extern "C" void kernel_launch(void* const* d_in, const int* in_sizes, int n_in,
                              void* d_out, int out_size)
{
    const float* hidden  = (const float*)d_in[0];
    const float* gst_emb = (const float*)d_in[1];
    const float* attn_w  = (const float*)d_in[2];
    const float* attn_b  = (const float*)d_in[3];
    const float* v       = (const float*)d_in[4];
    const float* out_w   = (const float*)d_in[5];
    const float* out_b   = (const float*)d_in[6];
    float* out  = (float*)d_out;
    float* att  = out;                   // [B, C*G]
    float* outp = out + B_ * C_ * G_;    // [B, O]

    cudaFuncSetAttribute(gemm_mma_kernel,
                         cudaFuncAttributeMaxDynamicSharedMemorySize, GSMEM);

    // Launch order chosen so convert_w sits in the ncu capture slot (4th launch).
    convert_a_kernel     <<<128,  256>>>(hidden);
    vsum_kernel          <<<C_,   256>>>(v);
    ebias_kernel         <<<dim3(C_, 8), 256>>>(gst_emb, attn_w, attn_b);
    convert_w_kernel     <<<8192, 256>>>(attn_w);
    gemm_mma_kernel      <<<dim3(8, 2, C_), 256, GSMEM>>>();
    scores_softmax_kernel<<<dim3(C_, 16), 256>>>(v, att);
    pooled_kernel        <<<B_ / 4, 256>>>(att, gst_emb);
    out_kernel           <<<B_ / 8, 256>>>(out_w, out_b, outp);
}

// round 11
// speedup vs baseline: 1.1843x; 1.0076x over previous
#include <cuda_runtime.h>
#include <cuda_bf16.h>
#include <cstdint>

#define B_ 256
#define H_ 1024
#define D_ 256
#define C_ 16
#define G_ 32
#define O_ 256
#define HD_ 1280  // H + D

// ---------------- device-global scratch (no cudaMalloc allowed) ----------------
__device__ float g_hid[B_ * C_ * H_];      // [b][c][h]  = exp2(2.885 * hid_part)
__device__ float g_ebias[C_ * G_ * H_];    // [c][g][h]  = exp2(2.885 * (enc_part + bias))
__device__ float g_pooled[B_ * D_];        // [b][d]
__device__ float g_vsum[C_];               // [c] = sum_h v[c][h]

// bf16 hi/lo split operands, plain row-major (k contiguous).
__device__ uint4 g_ah[B_ * H_ / 8];            // A hi  [m][k]   0.5 MB
__device__ uint4 g_al[B_ * H_ / 8];            // A lo
__device__ uint4 g_wh[C_ * H_ * H_ / 8];       // W hi  [c][n][k]  32 MB
__device__ uint4 g_wl[C_ * H_ * H_ / 8];       // W lo

// ---------------- helpers ----------------
__device__ __forceinline__ uint32_t smem_u32(const void* p) {
    uint32_t a;
    asm("{ .reg .u64 t; cvta.to.shared.u64 t, %1; cvt.u32.u64 %0, t; }"
        : "=r"(a) : "l"(p));
    return a;
}
__device__ __forceinline__ void cp16(uint32_t dst, const void* src) {
    asm volatile("cp.async.cg.shared.global [%0], [%1], 16;"
                 :: "r"(dst), "l"(src) : "memory");
}
__device__ __forceinline__ void ldsm4(uint32_t* r, uint32_t addr) {
    asm volatile("ldmatrix.sync.aligned.m8n8.x4.shared.b16 {%0,%1,%2,%3}, [%4];"
                 : "=r"(r[0]), "=r"(r[1]), "=r"(r[2]), "=r"(r[3]) : "r"(addr));
}
__device__ __forceinline__ void mma16816(float* d, const uint32_t* a, const uint32_t* b) {
    asm volatile(
        "mma.sync.aligned.m16n8k16.row.col.f32.bf16.bf16.f32 "
        "{%0,%1,%2,%3}, {%4,%5,%6,%7}, {%8,%9}, {%0,%1,%2,%3};"
        : "+f"(d[0]), "+f"(d[1]), "+f"(d[2]), "+f"(d[3])
        : "r"(a[0]), "r"(a[1]), "r"(a[2]), "r"(a[3]), "r"(b[0]), "r"(b[1]));
}
// exp2 via MUFU
__device__ __forceinline__ float ex2f(float x) {
    float r;
    asm("ex2.approx.f32 %0, %1;" : "=f"(r) : "f"(x));
    return r;
}
#define TANH_SCALE 2.8853900817779268f   // 2 * log2(e)

// packed fp32x2
__device__ __forceinline__ unsigned long long pack2f(float x, float y) {
    unsigned long long r;
    asm("mov.b64 %0, {%1, %2};" : "=l"(r) : "f"(x), "f"(y));
    return r;
}
__device__ __forceinline__ void unpack2f(unsigned long long p, float& x, float& y) {
    asm("mov.b64 {%0, %1}, %2;" : "=f"(x), "=f"(y) : "l"(p));
}

__device__ __forceinline__ void split8(const float* xs, uint32_t* hw, uint32_t* lw) {
    #pragma unroll
    for (int i = 0; i < 4; i++) {
        __nv_bfloat16 h0 = __float2bfloat16(xs[2*i]);
        __nv_bfloat16 h1 = __float2bfloat16(xs[2*i+1]);
        __nv_bfloat16 l0 = __float2bfloat16(xs[2*i]   - __bfloat162float(h0));
        __nv_bfloat16 l1 = __float2bfloat16(xs[2*i+1] - __bfloat162float(h1));
        hw[i] = (uint32_t)__bfloat16_as_ushort(h0) | ((uint32_t)__bfloat16_as_ushort(h1) << 16);
        lw[i] = (uint32_t)__bfloat16_as_ushort(l0) | ((uint32_t)__bfloat16_as_ushort(l1) << 16);
    }
}

// ---------------- K0 fused: conv_a (blocks 0-127) | ebias (128-255) | vsum (256-271)
__global__ void __launch_bounds__(256) pre_kernel(
    const float* __restrict__ hidden, const float* __restrict__ gst_emb,
    const float* __restrict__ attn_w, const float* __restrict__ attn_b,
    const float* __restrict__ v)
{
    __shared__ float gs[G_][D_];
    int bx = blockIdx.x;
    int t = threadIdx.x;

    if (bx < 128) {
        // ---- conv_a: split hidden -> bf16 hi/lo ----
        int idx = bx * 256 + t;
        int b = idx >> 7, j = idx & 127;
        const float4* s = (const float4*)(hidden + (size_t)b * H_ + j * 8);
        float4 x0 = s[0], x1 = s[1];
        float xs[8] = {x0.x, x0.y, x0.z, x0.w, x1.x, x1.y, x1.z, x1.w};
        uint32_t hw[4], lw[4];
        split8(xs, hw, lw);
        g_ah[b * 128 + j] = make_uint4(hw[0], hw[1], hw[2], hw[3]);
        g_al[b * 128 + j] = make_uint4(lw[0], lw[1], lw[2], lw[3]);
    } else if (bx < 256) {
        // ---- ebias -> exp2 domain ----
        int idx2 = bx - 128;
        int c = idx2 & 15, ob = idx2 >> 4;
        int o = ob * 128 + (t & 127);
        int gbase = (t >> 7) * 16;
        const float4* src = (const float4*)(gst_emb + (size_t)c * G_ * D_);
        for (int i = t; i < G_ * D_ / 4; i += 256)
            ((float4*)gs)[i] = src[i];
        __syncthreads();

        float acc[16];
        #pragma unroll
        for (int g = 0; g < 16; g++) acc[g] = 0.f;

        const float* wrow = attn_w + (size_t)c * H_ * HD_ + (size_t)o * HD_ + H_;
        for (int d = 0; d < D_; d += 4) {
            float4 w4 = *(const float4*)(wrow + d);
            #pragma unroll
            for (int g = 0; g < 16; g++) {
                float a = acc[g];
                a = fmaf(gs[gbase + g][d],     w4.x, a);
                a = fmaf(gs[gbase + g][d + 1], w4.y, a);
                a = fmaf(gs[gbase + g][d + 2], w4.z, a);
                a = fmaf(gs[gbase + g][d + 3], w4.w, a);
                acc[g] = a;
            }
        }
        float bias = attn_b[c * H_ + o];
        #pragma unroll
        for (int g = 0; g < 16; g++)
            g_ebias[(size_t)c * G_ * H_ + (size_t)(gbase + g) * H_ + o] =
                ex2f((acc[g] + bias) * TANH_SCALE);
    } else {
        // ---- vsum ----
        int c = bx - 256;
        float s = 0.f;
        #pragma unroll
        for (int p = 0; p < 4; p++) s += v[(size_t)c * H_ + t + p * 256];
        #pragma unroll
        for (int off = 16; off > 0; off >>= 1)
            s += __shfl_xor_sync(0xffffffffu, s, off);
        __shared__ float ws[8];
        if ((t & 31) == 0) ws[t >> 5] = s;
        __syncthreads();
        if (t == 0) {
            float tot = 0.f;
            #pragma unroll
            for (int i = 0; i < 8; i++) tot += ws[i];
            g_vsum[c] = tot;
        }
    }
}

// ---------------- K0b: split w_hid -> bf16 hi/lo ----------------
__global__ void __launch_bounds__(256) convert_w_kernel(const float* __restrict__ attn_w)
{
    int idx = blockIdx.x * 256 + threadIdx.x;   // 2,097,152
    int j = idx & 127;
    int o = (idx >> 7) & 1023;
    int c = idx >> 17;
    const float4* s = (const float4*)(attn_w + ((size_t)c * H_ + o) * HD_ + j * 8);
    float4 x0 = s[0], x1 = s[1];
    float xs[8] = {x0.x, x0.y, x0.z, x0.w, x1.x, x1.y, x1.z, x1.w};
    uint32_t hw[4], lw[4];
    split8(xs, hw, lw);
    size_t u = (size_t)c * 131072 + (size_t)o * 128 + j;
    g_wh[u] = make_uint4(hw[0], hw[1], hw[2], hw[3]);
    g_wl[u] = make_uint4(lw[0], lw[1], lw[2], lw[3]);
}

// ---------------- K2: hid_part GEMM via mma.sync bf16 hi/lo ----------------
#define LDROW 80
#define TILEB (128 * LDROW)
#define STAGEB (4 * TILEB)
#define GSMEM (2 * STAGEB)          // 81920
#define NKC 32

__global__ void __launch_bounds__(256) gemm_mma_kernel()
{
    extern __shared__ char smem[];
    uint32_t sb = smem_u32(smem);
    int t = threadIdx.x, w = t >> 5, l = t & 31;
    int wm = w & 1, wn = w >> 1;
    int bn0 = blockIdx.x * 128, bm0 = blockIdx.y * 128, c = blockIdx.z;

    const uint4* pAh = g_ah + (size_t)bm0 * 128;
    const uint4* pAl = g_al + (size_t)bm0 * 128;
    const uint4* pBh = g_wh + (size_t)c * 131072 + (size_t)bn0 * 128;
    const uint4* pBl = g_wl + (size_t)c * 131072 + (size_t)bn0 * 128;

    int row = t >> 2, q = t & 3;
    uint32_t cpdst = (uint32_t)(row * LDROW + q * 16);

    float acc[4][4][4];
    #pragma unroll
    for (int i = 0; i < 4; i++)
        #pragma unroll
        for (int j = 0; j < 4; j++)
            #pragma unroll
            for (int k = 0; k < 4; k++) acc[i][j][k] = 0.f;

    auto stage_load = [&](int kc, int buf) {
        uint32_t base = sb + buf * STAGEB;
        #pragma unroll
        for (int h = 0; h < 2; h++) {
            int r = row + h * 64;
            int su = r * 128 + kc * 4 + q;
            uint32_t d = base + cpdst + h * 64 * LDROW;
            cp16(d,              pAh + su);
            cp16(d + TILEB,      pAl + su);
            cp16(d + 2 * TILEB,  pBh + su);
            cp16(d + 3 * TILEB,  pBl + su);
        }
        asm volatile("cp.async.commit_group;" ::: "memory");
    };

    stage_load(0, 0);

    uint32_t arow_off = (uint32_t)((l & 15) * LDROW + (l >> 4) * 16);
    uint32_t brow_off = (uint32_t)((((l & 7) + ((l >> 4) << 3)) * LDROW) + ((l >> 3) & 1) * 16);

    for (int kc = 0; kc < NKC; kc++) {
        int cur = kc & 1;
        if (kc + 1 < NKC) {
            stage_load(kc + 1, cur ^ 1);
            asm volatile("cp.async.wait_group 1;" ::: "memory");
        } else {
            asm volatile("cp.async.wait_group 0;" ::: "memory");
        }
        __syncthreads();

        uint32_t base = sb + cur * STAGEB;
        #pragma unroll
        for (int kk = 0; kk < 2; kk++) {
            uint32_t kkb = kk * 32;
            uint32_t aH[4][4], aL[4][4], bH[2][4], bL[2][4];
            #pragma unroll
            for (int mt = 0; mt < 4; mt++) {
                uint32_t ad = base + (uint32_t)((wm * 64 + mt * 16) * LDROW) + kkb + arow_off;
                ldsm4(aH[mt], ad);
                ldsm4(aL[mt], ad + TILEB);
            }
            #pragma unroll
            for (int p = 0; p < 2; p++) {
                uint32_t bd = base + 2 * TILEB +
                              (uint32_t)((wn * 32 + p * 16) * LDROW) + kkb + brow_off;
                ldsm4(bH[p], bd);
                ldsm4(bL[p], bd + TILEB);
            }
            #pragma unroll
            for (int mt = 0; mt < 4; mt++)
                #pragma unroll
                for (int p = 0; p < 2; p++)
                    #pragma unroll
                    for (int hf = 0; hf < 2; hf++) {
                        int nt = p * 2 + hf;
                        mma16816(acc[mt][nt], aH[mt], &bH[p][hf * 2]);
                        mma16816(acc[mt][nt], aH[mt], &bL[p][hf * 2]);
                        mma16816(acc[mt][nt], aL[mt], &bH[p][hf * 2]);
                    }
        }
        __syncthreads();
    }

    // epilogue: Eh = exp2(2.885 * acc) -> g_hid[b][c][h]
    #pragma unroll
    for (int mt = 0; mt < 4; mt++) {
        int m0 = bm0 + wm * 64 + mt * 16 + (l >> 2);
        #pragma unroll
        for (int nt = 0; nt < 4; nt++) {
            int col = bn0 + wn * 32 + nt * 8 + (l & 3) * 2;
            float* d0 = g_hid + (size_t)m0 * (C_ * H_) + (size_t)c * H_ + col;
            *(float2*)d0 = make_float2(ex2f(acc[mt][nt][0] * TANH_SCALE),
                                       ex2f(acc[mt][nt][1] * TANH_SCALE));
            *(float2*)(d0 + (size_t)8 * C_ * H_) =
                make_float2(ex2f(acc[mt][nt][2] * TANH_SCALE),
                            ex2f(acc[mt][nt][3] * TANH_SCALE));
        }
    }
}

// ---------------- K3: fused scores + softmax, 512 threads, 1 b-row per warp ----------------
// score = Vsum + sum_j (-2 v_j) * rcp(1 + Eh*Ee).
// 16 warps = 16 b rows per block; lane = g. 3-4 blocks/SM -> ~48-64 warps/SM.
__global__ void __launch_bounds__(512) scores_softmax_kernel(
    const float* __restrict__ v, float* __restrict__ att)
{
    int c = blockIdx.x;
    int b0 = blockIdx.y * 16;
    __shared__ float ehS[16][130];
    __shared__ float eeS[32][130];
    __shared__ float w2S[128];       // -2 * v
    int t = threadIdx.x;
    int g = t & 31;
    int bb = t >> 5;                 // warp id = b row 0..15

    unsigned long long acc2 = pack2f(0.f, 0.f);
    const unsigned long long ONE2 = pack2f(1.f, 1.f);

    for (int hc = 0; hc < H_; hc += 128) {
        #pragma unroll
        for (int p = 0; p < 2; p++) {   // Eh tile: 16 rows x 128 (1024 float2)
            int idx = t + p * 512;
            int r = idx >> 6, j2 = idx & 63;
            float2 hv = *(const float2*)(g_hid + (size_t)(b0 + r) * (C_ * H_) +
                                         (size_t)c * H_ + hc + j2 * 2);
            *(float2*)&ehS[r][j2 * 2] = hv;
        }
        #pragma unroll
        for (int p = 0; p < 4; p++) {   // Ee tile: 32 rows x 128 (2048 float2)
            int idx = t + p * 512;
            int r = idx >> 6, j2 = idx & 63;
            float2 ev = *(const float2*)(g_ebias + (size_t)c * (G_ * H_) +
                                         (size_t)r * H_ + hc + j2 * 2);
            *(float2*)&eeS[r][j2 * 2] = ev;
        }
        if (t < 64) {
            float2 vv = *(const float2*)(v + (size_t)c * H_ + hc + t * 2);
            *(float2*)&w2S[t * 2] = make_float2(-2.f * vv.x, -2.f * vv.y);
        }
        __syncthreads();

        #pragma unroll 8
        for (int j2 = 0; j2 < 64; j2++) {
            unsigned long long ee2 = *(const unsigned long long*)&eeS[g][j2 * 2];
            unsigned long long eh2 = *(const unsigned long long*)&ehS[bb][j2 * 2];
            unsigned long long w2  = *(const unsigned long long*)&w2S[j2 * 2];
            unsigned long long d2;
            asm("fma.rn.f32x2 %0, %1, %2, %3;" : "=l"(d2) : "l"(eh2), "l"(ee2), "l"(ONE2));
            float d0, d1, r0, r1;
            unpack2f(d2, d0, d1);
            asm("rcp.approx.f32 %0, %1;" : "=f"(r0) : "f"(d0));
            asm("rcp.approx.f32 %0, %1;" : "=f"(r1) : "f"(d1));
            unsigned long long r2 = pack2f(r0, r1);
            asm("fma.rn.f32x2 %0, %1, %2, %0;" : "+l"(acc2) : "l"(w2), "l"(r2));
        }
        __syncthreads();
    }

    float x0, x1;
    unpack2f(acc2, x0, x1);
    float s = g_vsum[c] + x0 + x1;

    // warp softmax over g (lanes)
    float m = s;
    #pragma unroll
    for (int off = 16; off > 0; off >>= 1)
        m = fmaxf(m, __shfl_xor_sync(0xffffffffu, m, off));
    float e = __expf(s - m);
    float sum = e;
    #pragma unroll
    for (int off = 16; off > 0; off >>= 1)
        sum += __shfl_xor_sync(0xffffffffu, sum, off);
    att[(size_t)(b0 + bb) * (C_ * G_) + c * G_ + g] = e / sum;
}

// ---------------- K4b: pooled ----------------
__global__ void __launch_bounds__(256) pooled_kernel(
    const float* __restrict__ att, const float* __restrict__ gst_emb)
{
    int b0 = blockIdx.x * 4;
    int d = threadIdx.x;
    __shared__ float attS[4][C_ * G_];
    #pragma unroll
    for (int p = 0; p < 8; p++) {
        int idx = threadIdx.x + p * 256;
        attS[idx >> 9][idx & 511] = att[(size_t)b0 * 512 + idx];
    }
    __syncthreads();
    float acc[4];
    #pragma unroll
    for (int i = 0; i < 4; i++) acc[i] = 0.f;
    #pragma unroll 4
    for (int cg = 0; cg < C_ * G_; cg++) {
        float e = gst_emb[(size_t)cg * D_ + d];
        #pragma unroll
        for (int i = 0; i < 4; i++) acc[i] = fmaf(attS[i][cg], e, acc[i]);
    }
    #pragma unroll
    for (int i = 0; i < 4; i++)
        g_pooled[(size_t)(b0 + i) * D_ + d] = acc[i] * (1.0f / C_);
}

// ---------------- K4c: out ----------------
__global__ void __launch_bounds__(256) out_kernel(
    const float* __restrict__ out_w, const float* __restrict__ out_b,
    float* __restrict__ outp)
{
    int b0 = blockIdx.x * 8;
    int o = threadIdx.x;
    __shared__ float ps[8][D_];
    #pragma unroll
    for (int p = 0; p < 8; p++) {
        int idx = threadIdx.x + p * 256;
        ps[idx >> 8][idx & 255] = g_pooled[(size_t)b0 * D_ + idx];
    }
    __syncthreads();
    float acc[8];
    #pragma unroll
    for (int i = 0; i < 8; i++) acc[i] = 0.f;
    const float* wrow = out_w + (size_t)o * D_;
    for (int dd = 0; dd < D_; dd += 4) {
        float4 w4 = *(const float4*)(wrow + dd);
        #pragma unroll
        for (int i = 0; i < 8; i++) {
            float a = acc[i];
            a = fmaf(ps[i][dd],     w4.x, a);
            a = fmaf(ps[i][dd + 1], w4.y, a);
            a = fmaf(ps[i][dd + 2], w4.z, a);
            a = fmaf(ps[i][dd + 3], w4.w, a);
            acc[i] = a;
        }
    }
    float bias = out_b[o];
    #pragma unroll
    for (int i = 0; i < 8; i++)
        outp[(size_t)(b0 + i) * O_ + o] = acc[i] + bias;
}

extern "C" void kernel_launch(void* const* d_in, const int* in_sizes, int n_in,
                              void* d_out, int out_size)
{
    const float* hidden  = (const float*)d_in[0];
    const float* gst_emb = (const float*)d_in[1];
    const float* attn_w  = (const float*)d_in[2];
    const float* attn_b  = (const float*)d_in[3];
    const float* v       = (const float*)d_in[4];
    const float* out_w   = (const float*)d_in[5];
    const float* out_b   = (const float*)d_in[6];
    float* out  = (float*)d_out;
    float* att  = out;                   // [B, C*G]
    float* outp = out + B_ * C_ * G_;    // [B, O]

    cudaFuncSetAttribute(gemm_mma_kernel,
                         cudaFuncAttributeMaxDynamicSharedMemorySize, GSMEM);

    // Launch order: scores sits in the ncu capture slot (4th launch).
    pre_kernel           <<<272,  256>>>(hidden, gst_emb, attn_w, attn_b, v);
    convert_w_kernel     <<<8192, 256>>>(attn_w);
    gemm_mma_kernel      <<<dim3(8, 2, C_), 256, GSMEM>>>();
    scores_softmax_kernel<<<dim3(C_, 16), 512>>>(v, att);
    pooled_kernel        <<<B_ / 4, 256>>>(att, gst_emb);
    out_kernel           <<<B_ / 8, 256>>>(out_w, out_b, outp);
}